// round 5
// baseline (speedup 1.0000x reference)
#include <cuda_runtime.h>
#include <cuda_bf16.h>
#include <cstdint>

#define BATCH_MAX 10000
#define FEAT 256
#define EMB  256
#define NSAMP 32
#define FULLMASK 0xFFFFFFFFu

// Scratch
__device__ float g_Mb[FEAT * EMB];       // big(Wq@Wk^T), n-major k-permuted
__device__ float g_Ml[FEAT * EMB];       // small part
__device__ float g_Wvb[FEAT * EMB];      // big(Wv), n-major k-permuted
__device__ float g_Wvl[FEAT * EMB];
__device__ float g_bqk[FEAT];            // bq @ Wk^T
__device__ float g_qt[BATCH_MAX * FEAT]; // q-tilde
__device__ float g_agg[BATCH_MAX * FEAT];// softmax-weighted feature agg

// k-permutation within each 8-group: frag pair (t, t+4) -> adjacent (2t, 2t+1)
__device__ __forceinline__ int kpos(int k) {
    return (k & ~7) | ((k & 3) << 1) | ((k & 7) >> 2);
}

__device__ __forceinline__ void tf32_split(float x, uint32_t& hi, uint32_t& lo) {
    uint32_t b;
    asm("cvt.rna.tf32.f32 %0, %1;" : "=r"(b) : "f"(x));
    float r = x - __uint_as_float(b);
    uint32_t s;
    asm("cvt.rna.tf32.f32 %0, %1;" : "=r"(s) : "f"(r));
    hi = b; lo = s;
}

__device__ __forceinline__ void mma_tf32(float* d, const uint32_t* a, const uint32_t* b) {
    asm("mma.sync.aligned.m16n8k8.row.col.f32.tf32.tf32.f32 "
        "{%0,%1,%2,%3},{%4,%5,%6,%7},{%8,%9},{%0,%1,%2,%3};"
        : "+f"(d[0]), "+f"(d[1]), "+f"(d[2]), "+f"(d[3])
        : "r"(a[0]), "r"(a[1]), "r"(a[2]), "r"(a[3]), "r"(b[0]), "r"(b[1]));
}

// ---------------------------------------------------------------------------
// M = Wq @ Wk^T (fp32-exact), emitted pre-split into n-major k-permuted layout
// ---------------------------------------------------------------------------
__global__ void k_wqwkT(const float* __restrict__ Wq, const float* __restrict__ Wk,
                        float* __restrict__ Mb, float* __restrict__ Ml) {
    __shared__ float a[16][17];
    __shared__ float b[16][17];
    int tx = threadIdx.x, ty = threadIdx.y;
    int i = blockIdx.y * 16 + ty;   // k-dim of the downstream GEMM
    int j0 = blockIdx.x * 16;
    float acc = 0.f;
    for (int e0 = 0; e0 < FEAT; e0 += 16) {
        a[ty][tx] = Wq[i * FEAT + e0 + tx];
        b[ty][tx] = Wk[(j0 + ty) * FEAT + e0 + tx];
        __syncthreads();
        #pragma unroll
        for (int k = 0; k < 16; k++) acc += a[ty][k] * b[tx][k];
        __syncthreads();
    }
    uint32_t hi, lo;
    tf32_split(acc, hi, lo);
    int p = (j0 + tx) * FEAT + kpos(i);
    Mb[p] = __uint_as_float(hi);
    Ml[p] = __uint_as_float(lo);
}

// ---------------------------------------------------------------------------
// Split Wv [k][n] into n-major k-permuted big/small arrays
// ---------------------------------------------------------------------------
__global__ void k_splitW(const float* __restrict__ W,
                         float* __restrict__ Wb, float* __restrict__ Wl) {
    int k = blockIdx.x, n = threadIdx.x;
    float v = W[k * EMB + n];
    uint32_t hi, lo;
    tf32_split(v, hi, lo);
    int p = n * FEAT + kpos(k);
    Wb[p] = __uint_as_float(hi);
    Wl[p] = __uint_as_float(lo);
}

// ---------------------------------------------------------------------------
// bqk[j] = bq . Wk[j,:]
// ---------------------------------------------------------------------------
__global__ void k_bqk(const float* __restrict__ Wk, const float* __restrict__ bq,
                      float* __restrict__ bqk) {
    int j = blockIdx.x * 8 + (threadIdx.x >> 5);
    int lane = threadIdx.x & 31;
    float s = 0.f;
    #pragma unroll
    for (int e = lane; e < FEAT; e += 32) s += bq[e] * Wk[j * FEAT + e];
    #pragma unroll
    for (int o = 16; o; o >>= 1) s += __shfl_down_sync(FULLMASK, s, o);
    if (lane == 0) bqk[j] = s;
}

// ---------------------------------------------------------------------------
// Tensor-core GEMM (3xTF32, pre-split operands):
//   C[r][j] = sum_k A[row(r)][k]*B[k][j] + bias[j]
//   BM=128, BN=64, BK=32. 256 threads = 8 warps (4m x 2n), warp tile 32x32.
//   B pre-split in global (n-major, k-permuted) -> LDG.64 frag pairs, L1-hot.
//   A split once at smem-store time into As_b/As_l (k-permuted) -> LDS.64 pairs.
// ---------------------------------------------------------------------------
template <bool GATHER>
__global__ void __launch_bounds__(256) k_gemm_tc(
    const float* __restrict__ A, const int* __restrict__ idx,
    const float* __restrict__ Bb, const float* __restrict__ Bl,
    const float* __restrict__ bias, float* __restrict__ C, int R) {
    __shared__ float As_b[128][36];
    __shared__ float As_l[128][36];
    int tid = threadIdx.x;
    int wid = tid >> 5, lane = tid & 31;
    int g = lane >> 2, t = lane & 3;
    int wm = wid & 3, wn = wid >> 2;
    int r0 = blockIdx.y * 128, c0 = blockIdx.x * 64;

    // A loader: 2 threads per row, 16 consecutive floats each
    int la_row = tid >> 1;
    int la_q = (tid & 1) * 16;   // k offset within 32-chunk: 0 or 16
    int gr = r0 + la_row;
    bool av = gr < R;
    int grow = av ? (GATHER ? __ldg(idx + gr) : gr) : 0;
    const float* Arow = A + (size_t)grow * FEAT;

    float acc[2][4][4];
    #pragma unroll
    for (int mf = 0; mf < 2; mf++)
        #pragma unroll
        for (int nf = 0; nf < 4; nf++)
            #pragma unroll
            for (int q = 0; q < 4; q++) acc[mf][nf][q] = 0.f;

    float4 aR[4];
    #pragma unroll
    for (int q = 0; q < 4; q++)
        aR[q] = av ? *(const float4*)(Arow + la_q + q * 4)
                   : make_float4(0.f, 0.f, 0.f, 0.f);

    for (int kt = 0; kt < FEAT / 32; kt++) {
        if (kt) __syncthreads();
        #pragma unroll
        for (int q = 0; q < 4; q++) {
            float vals[4] = {aR[q].x, aR[q].y, aR[q].z, aR[q].w};
            #pragma unroll
            for (int e = 0; e < 4; e++) {
                int j = la_q + q * 4 + e;       // 0..31 within chunk
                int p = kpos(j);
                uint32_t hi, lo;
                tf32_split(vals[e], hi, lo);
                As_b[la_row][p] = __uint_as_float(hi);
                As_l[la_row][p] = __uint_as_float(lo);
            }
        }
        __syncthreads();
        if (kt < FEAT / 32 - 1) {
            #pragma unroll
            for (int q = 0; q < 4; q++)
                aR[q] = av ? *(const float4*)(Arow + (kt + 1) * 32 + la_q + q * 4)
                           : make_float4(0.f, 0.f, 0.f, 0.f);
        }
        #pragma unroll
        for (int ks = 0; ks < 4; ks++) {
            int kc = ks * 8 + 2 * t;
            uint32_t Ab[2][4], Al[2][4];
            #pragma unroll
            for (int mf = 0; mf < 2; mf++) {
                int rb = wm * 32 + mf * 16;
                float2 h0 = *(const float2*)&As_b[rb + g][kc];
                float2 h1 = *(const float2*)&As_b[rb + 8 + g][kc];
                float2 l0 = *(const float2*)&As_l[rb + g][kc];
                float2 l1 = *(const float2*)&As_l[rb + 8 + g][kc];
                Ab[mf][0] = __float_as_uint(h0.x); Ab[mf][1] = __float_as_uint(h1.x);
                Ab[mf][2] = __float_as_uint(h0.y); Ab[mf][3] = __float_as_uint(h1.y);
                Al[mf][0] = __float_as_uint(l0.x); Al[mf][1] = __float_as_uint(l1.x);
                Al[mf][2] = __float_as_uint(l0.y); Al[mf][3] = __float_as_uint(l1.y);
            }
            #pragma unroll
            for (int nf = 0; nf < 4; nf++) {
                int nb = c0 + wn * 32 + nf * 8 + g;
                size_t boff = (size_t)nb * FEAT + kt * 32 + kc;
                float2 bb = __ldg((const float2*)(Bb + boff));
                float2 bl = __ldg((const float2*)(Bl + boff));
                uint32_t Bbf[2] = {__float_as_uint(bb.x), __float_as_uint(bb.y)};
                uint32_t Blf[2] = {__float_as_uint(bl.x), __float_as_uint(bl.y)};
                #pragma unroll
                for (int mf = 0; mf < 2; mf++) {
                    mma_tf32(acc[mf][nf], Ab[mf], Bbf);
                    mma_tf32(acc[mf][nf], Ab[mf], Blf);
                    mma_tf32(acc[mf][nf], Al[mf], Bbf);
                }
            }
        }
    }

    #pragma unroll
    for (int mf = 0; mf < 2; mf++) {
        int r_lo = r0 + wm * 32 + mf * 16 + g;
        int r_hi = r_lo + 8;
        #pragma unroll
        for (int nf = 0; nf < 4; nf++) {
            int c = c0 + wn * 32 + nf * 8 + 2 * t;
            float b0 = bias[c], b1 = bias[c + 1];
            if (r_lo < R) {
                float2 v = make_float2(acc[mf][nf][0] + b0, acc[mf][nf][1] + b1);
                *(float2*)(C + (size_t)r_lo * EMB + c) = v;
            }
            if (r_hi < R) {
                float2 v = make_float2(acc[mf][nf][2] + b0, acc[mf][nf][3] + b1);
                *(float2*)(C + (size_t)r_hi * EMB + c) = v;
            }
        }
    }
}

// ---------------------------------------------------------------------------
// Attention: one block per batch row; features stay in registers.
// Softmax computed redundantly in every warp (no warp0 serialization).
// ---------------------------------------------------------------------------
__global__ void __launch_bounds__(256) k_attn(
    const float* __restrict__ id2feat, const int* __restrict__ neigh,
    const float* __restrict__ qt, float* __restrict__ agg) {
    __shared__ __align__(16) float sq[FEAT];
    __shared__ float sscore[NSAMP];
    __shared__ __align__(16) float spart[8][FEAT];

    int b = blockIdx.x;
    int tid = threadIdx.x;
    int w = tid >> 5, lane = tid & 31;

    sq[tid] = qt[(size_t)b * FEAT + tid];
    __syncthreads();

    const float4* q4 = (const float4*)sq;
    float4 q0 = q4[lane];
    float4 q1 = q4[lane + 32];

    float4 f[4][2];
    #pragma unroll
    for (int si = 0; si < 4; si++) {
        int s = w * 4 + si;
        int idx = __ldg(neigh + (size_t)b * NSAMP + s);
        const float4* row = (const float4*)(id2feat + (size_t)idx * FEAT);
        f[si][0] = row[lane];
        f[si][1] = row[lane + 32];
        float acc = f[si][0].x * q0.x + f[si][0].y * q0.y +
                    f[si][0].z * q0.z + f[si][0].w * q0.w +
                    f[si][1].x * q1.x + f[si][1].y * q1.y +
                    f[si][1].z * q1.z + f[si][1].w * q1.w;
        #pragma unroll
        for (int o = 16; o; o >>= 1) acc += __shfl_down_sync(FULLMASK, acc, o);
        if (lane == 0) sscore[s] = acc;
    }
    __syncthreads();

    // per-warp redundant softmax over the 32 scores
    float sc = sscore[lane];
    float m = sc;
    #pragma unroll
    for (int o = 16; o; o >>= 1) m = fmaxf(m, __shfl_xor_sync(FULLMASK, m, o));
    float e = __expf(sc - m);
    float sum = e;
    #pragma unroll
    for (int o = 16; o; o >>= 1) sum += __shfl_xor_sync(FULLMASK, sum, o);
    float aval = e / sum;

    float a0 = __shfl_sync(FULLMASK, aval, w * 4 + 0);
    float a1 = __shfl_sync(FULLMASK, aval, w * 4 + 1);
    float a2 = __shfl_sync(FULLMASK, aval, w * 4 + 2);
    float a3 = __shfl_sync(FULLMASK, aval, w * 4 + 3);

    float4 p0, p1;
    p0.x = f[0][0].x * a0 + f[1][0].x * a1 + f[2][0].x * a2 + f[3][0].x * a3;
    p0.y = f[0][0].y * a0 + f[1][0].y * a1 + f[2][0].y * a2 + f[3][0].y * a3;
    p0.z = f[0][0].z * a0 + f[1][0].z * a1 + f[2][0].z * a2 + f[3][0].z * a3;
    p0.w = f[0][0].w * a0 + f[1][0].w * a1 + f[2][0].w * a2 + f[3][0].w * a3;
    p1.x = f[0][1].x * a0 + f[1][1].x * a1 + f[2][1].x * a2 + f[3][1].x * a3;
    p1.y = f[0][1].y * a0 + f[1][1].y * a1 + f[2][1].y * a2 + f[3][1].y * a3;
    p1.z = f[0][1].z * a0 + f[1][1].z * a1 + f[2][1].z * a2 + f[3][1].z * a3;
    p1.w = f[0][1].w * a0 + f[1][1].w * a1 + f[2][1].w * a2 + f[3][1].w * a3;
    ((float4*)spart[w])[lane] = p0;
    ((float4*)spart[w])[lane + 32] = p1;
    __syncthreads();

    float acc = 0.f;
    #pragma unroll
    for (int ww = 0; ww < 8; ww++) acc += spart[ww][tid];
    agg[(size_t)b * FEAT + tid] = acc;
}

// ---------------------------------------------------------------------------
extern "C" void kernel_launch(void* const* d_in, const int* in_sizes, int n_in,
                              void* d_out, int out_size) {
    const int*   nodes   = (const int*)d_in[0];
    const int*   neigh   = (const int*)d_in[1];
    const float* id2feat = (const float*)d_in[2];
    const float* Wq      = (const float*)d_in[3];
    const float* bq      = (const float*)d_in[4];
    const float* Wk      = (const float*)d_in[5];
    const float* Wv      = (const float*)d_in[7];
    const float* bv      = (const float*)d_in[8];
    float* out = (float*)d_out;

    int B = in_sizes[0];  // 10000

    float *gMb, *gMl, *gWvb, *gWvl, *gbqk, *gqt, *gagg;
    cudaGetSymbolAddress((void**)&gMb,  g_Mb);
    cudaGetSymbolAddress((void**)&gMl,  g_Ml);
    cudaGetSymbolAddress((void**)&gWvb, g_Wvb);
    cudaGetSymbolAddress((void**)&gWvl, g_Wvl);
    cudaGetSymbolAddress((void**)&gbqk, g_bqk);
    cudaGetSymbolAddress((void**)&gqt,  g_qt);
    cudaGetSymbolAddress((void**)&gagg, g_agg);

    // 1) M = Wq @ Wk^T (split) ; bqk = bq @ Wk^T ; split Wv
    k_wqwkT<<<dim3(16, 16), dim3(16, 16)>>>(Wq, Wk, gMb, gMl);
    k_bqk<<<FEAT / 8, 256>>>(Wk, bq, gbqk);
    k_splitW<<<FEAT, EMB>>>(Wv, gWvb, gWvl);

    // 2) qt = gather(self) @ M + bqk
    dim3 ggrid(EMB / 64, (B + 127) / 128);
    k_gemm_tc<true><<<ggrid, 256>>>(id2feat, nodes, gMb, gMl, gbqk, gqt, B);

    // 3) scores + softmax + weighted feature aggregation
    k_attn<<<B, 256>>>(id2feat, neigh, gqt, gagg);

    // 4) out = agg @ Wv + bv
    k_gemm_tc<false><<<ggrid, 256>>>(gagg, nullptr, gWvb, gWvl, bv, out, B);
}

// round 6
// speedup vs baseline: 1.0066x; 1.0066x over previous
#include <cuda_runtime.h>
#include <cuda_bf16.h>
#include <cstdint>

#define BATCH_MAX 10000
#define FEAT 256
#define EMB  256
#define NSAMP 32
#define FULLMASK 0xFFFFFFFFu

// Scratch
__device__ float g_Mb[FEAT * EMB];       // big(Wq@Wk^T), n-major k-permuted
__device__ float g_Ml[FEAT * EMB];       // small part
__device__ float g_Wvb[FEAT * EMB];      // big(Wv), n-major k-permuted
__device__ float g_Wvl[FEAT * EMB];
__device__ float g_bqk[FEAT];            // bq @ Wk^T
__device__ float g_qt[BATCH_MAX * FEAT]; // q-tilde
__device__ float g_agg[BATCH_MAX * FEAT];// softmax-weighted feature agg

// k-permutation within each 8-group: frag pair (t, t+4) -> adjacent (2t, 2t+1)
__device__ __forceinline__ int kpos(int k) {
    return (k & ~7) | ((k & 3) << 1) | ((k & 7) >> 2);
}

__device__ __forceinline__ void tf32_split(float x, uint32_t& hi, uint32_t& lo) {
    uint32_t b;
    asm("cvt.rna.tf32.f32 %0, %1;" : "=r"(b) : "f"(x));
    float r = x - __uint_as_float(b);
    uint32_t s;
    asm("cvt.rna.tf32.f32 %0, %1;" : "=r"(s) : "f"(r));
    hi = b; lo = s;
}

__device__ __forceinline__ void mma_tf32(float* d, const uint32_t* a, const uint32_t* b) {
    asm("mma.sync.aligned.m16n8k8.row.col.f32.tf32.tf32.f32 "
        "{%0,%1,%2,%3},{%4,%5,%6,%7},{%8,%9},{%0,%1,%2,%3};"
        : "+f"(d[0]), "+f"(d[1]), "+f"(d[2]), "+f"(d[3])
        : "r"(a[0]), "r"(a[1]), "r"(a[2]), "r"(a[3]), "r"(b[0]), "r"(b[1]));
}

// ---------------------------------------------------------------------------
// M = Wq @ Wk^T (fp32-exact), emitted pre-split into n-major k-permuted layout
// ---------------------------------------------------------------------------
__global__ void k_wqwkT(const float* __restrict__ Wq, const float* __restrict__ Wk,
                        float* __restrict__ Mb, float* __restrict__ Ml) {
    __shared__ float a[16][17];
    __shared__ float b[16][17];
    int tx = threadIdx.x, ty = threadIdx.y;
    int i = blockIdx.y * 16 + ty;   // k-dim of the downstream GEMM
    int j0 = blockIdx.x * 16;
    float acc = 0.f;
    for (int e0 = 0; e0 < FEAT; e0 += 16) {
        a[ty][tx] = Wq[i * FEAT + e0 + tx];
        b[ty][tx] = Wk[(j0 + ty) * FEAT + e0 + tx];
        __syncthreads();
        #pragma unroll
        for (int k = 0; k < 16; k++) acc += a[ty][k] * b[tx][k];
        __syncthreads();
    }
    uint32_t hi, lo;
    tf32_split(acc, hi, lo);
    int p = (j0 + tx) * FEAT + kpos(i);
    Mb[p] = __uint_as_float(hi);
    Ml[p] = __uint_as_float(lo);
}

// ---------------------------------------------------------------------------
// Split Wv [k][n] into n-major k-permuted big/small arrays
// ---------------------------------------------------------------------------
__global__ void k_splitW(const float* __restrict__ W,
                         float* __restrict__ Wb, float* __restrict__ Wl) {
    int k = blockIdx.x, n = threadIdx.x;
    float v = W[k * EMB + n];
    uint32_t hi, lo;
    tf32_split(v, hi, lo);
    int p = n * FEAT + kpos(k);
    Wb[p] = __uint_as_float(hi);
    Wl[p] = __uint_as_float(lo);
}

// ---------------------------------------------------------------------------
// bqk[j] = bq . Wk[j,:]
// ---------------------------------------------------------------------------
__global__ void k_bqk(const float* __restrict__ Wk, const float* __restrict__ bq,
                      float* __restrict__ bqk) {
    int j = blockIdx.x * 8 + (threadIdx.x >> 5);
    int lane = threadIdx.x & 31;
    float s = 0.f;
    #pragma unroll
    for (int e = lane; e < FEAT; e += 32) s += bq[e] * Wk[j * FEAT + e];
    #pragma unroll
    for (int o = 16; o; o >>= 1) s += __shfl_down_sync(FULLMASK, s, o);
    if (lane == 0) bqk[j] = s;
}

// ---------------------------------------------------------------------------
// Tensor-core GEMM (3xTF32, pre-split operands):
//   C[r][j] = sum_k A[row(r)][k]*B[k][j] + bias[j]
//   BM=128, BN=64, BK=32. 256 threads = 8 warps (4m x 2n), warp tile 32x32.
//   B pre-split in global (n-major, k-permuted) -> LDG.64 frag pairs, L1-hot.
//   A split once at smem-store time into As_b/As_l (k-permuted) -> LDS.64 pairs.
// ---------------------------------------------------------------------------
template <bool GATHER>
__global__ void __launch_bounds__(256) k_gemm_tc(
    const float* __restrict__ A, const int* __restrict__ idx,
    const float* __restrict__ Bb, const float* __restrict__ Bl,
    const float* __restrict__ bias, float* __restrict__ C, int R) {
    __shared__ float As_b[128][36];
    __shared__ float As_l[128][36];
    int tid = threadIdx.x;
    int wid = tid >> 5, lane = tid & 31;
    int g = lane >> 2, t = lane & 3;
    int wm = wid & 3, wn = wid >> 2;
    int r0 = blockIdx.y * 128, c0 = blockIdx.x * 64;

    // A loader: 2 threads per row, 16 consecutive floats each
    int la_row = tid >> 1;
    int la_q = (tid & 1) * 16;   // k offset within 32-chunk: 0 or 16
    int gr = r0 + la_row;
    bool av = gr < R;
    int grow = av ? (GATHER ? __ldg(idx + gr) : gr) : 0;
    const float* Arow = A + (size_t)grow * FEAT;

    float acc[2][4][4];
    #pragma unroll
    for (int mf = 0; mf < 2; mf++)
        #pragma unroll
        for (int nf = 0; nf < 4; nf++)
            #pragma unroll
            for (int q = 0; q < 4; q++) acc[mf][nf][q] = 0.f;

    float4 aR[4];
    #pragma unroll
    for (int q = 0; q < 4; q++)
        aR[q] = av ? *(const float4*)(Arow + la_q + q * 4)
                   : make_float4(0.f, 0.f, 0.f, 0.f);

    for (int kt = 0; kt < FEAT / 32; kt++) {
        if (kt) __syncthreads();
        #pragma unroll
        for (int q = 0; q < 4; q++) {
            float vals[4] = {aR[q].x, aR[q].y, aR[q].z, aR[q].w};
            #pragma unroll
            for (int e = 0; e < 4; e++) {
                int j = la_q + q * 4 + e;       // 0..31 within chunk
                int p = kpos(j);
                uint32_t hi, lo;
                tf32_split(vals[e], hi, lo);
                As_b[la_row][p] = __uint_as_float(hi);
                As_l[la_row][p] = __uint_as_float(lo);
            }
        }
        __syncthreads();
        if (kt < FEAT / 32 - 1) {
            #pragma unroll
            for (int q = 0; q < 4; q++)
                aR[q] = av ? *(const float4*)(Arow + (kt + 1) * 32 + la_q + q * 4)
                           : make_float4(0.f, 0.f, 0.f, 0.f);
        }
        #pragma unroll
        for (int ks = 0; ks < 4; ks++) {
            int kc = ks * 8 + 2 * t;
            uint32_t Ab[2][4], Al[2][4];
            #pragma unroll
            for (int mf = 0; mf < 2; mf++) {
                int rb = wm * 32 + mf * 16;
                float2 h0 = *(const float2*)&As_b[rb + g][kc];
                float2 h1 = *(const float2*)&As_b[rb + 8 + g][kc];
                float2 l0 = *(const float2*)&As_l[rb + g][kc];
                float2 l1 = *(const float2*)&As_l[rb + 8 + g][kc];
                Ab[mf][0] = __float_as_uint(h0.x); Ab[mf][1] = __float_as_uint(h1.x);
                Ab[mf][2] = __float_as_uint(h0.y); Ab[mf][3] = __float_as_uint(h1.y);
                Al[mf][0] = __float_as_uint(l0.x); Al[mf][1] = __float_as_uint(l1.x);
                Al[mf][2] = __float_as_uint(l0.y); Al[mf][3] = __float_as_uint(l1.y);
            }
            #pragma unroll
            for (int nf = 0; nf < 4; nf++) {
                int nb = c0 + wn * 32 + nf * 8 + g;
                size_t boff = (size_t)nb * FEAT + kt * 32 + kc;
                float2 bb = __ldg((const float2*)(Bb + boff));
                float2 bl = __ldg((const float2*)(Bl + boff));
                uint32_t Bbf[2] = {__float_as_uint(bb.x), __float_as_uint(bb.y)};
                uint32_t Blf[2] = {__float_as_uint(bl.x), __float_as_uint(bl.y)};
                #pragma unroll
                for (int mf = 0; mf < 2; mf++) {
                    mma_tf32(acc[mf][nf], Ab[mf], Bbf);
                    mma_tf32(acc[mf][nf], Ab[mf], Blf);
                    mma_tf32(acc[mf][nf], Al[mf], Bbf);
                }
            }
        }
    }

    #pragma unroll
    for (int mf = 0; mf < 2; mf++) {
        int r_lo = r0 + wm * 32 + mf * 16 + g;
        int r_hi = r_lo + 8;
        #pragma unroll
        for (int nf = 0; nf < 4; nf++) {
            int c = c0 + wn * 32 + nf * 8 + 2 * t;
            float b0 = bias[c], b1 = bias[c + 1];
            if (r_lo < R) {
                float2 v = make_float2(acc[mf][nf][0] + b0, acc[mf][nf][1] + b1);
                *(float2*)(C + (size_t)r_lo * EMB + c) = v;
            }
            if (r_hi < R) {
                float2 v = make_float2(acc[mf][nf][2] + b0, acc[mf][nf][3] + b1);
                *(float2*)(C + (size_t)r_hi * EMB + c) = v;
            }
        }
    }
}

// ---------------------------------------------------------------------------
// Attention: one block per batch row; features stay in registers.
// Softmax computed redundantly in every warp (no warp0 serialization).
// ---------------------------------------------------------------------------
__global__ void __launch_bounds__(256) k_attn(
    const float* __restrict__ id2feat, const int* __restrict__ neigh,
    const float* __restrict__ qt, float* __restrict__ agg) {
    __shared__ __align__(16) float sq[FEAT];
    __shared__ float sscore[NSAMP];
    __shared__ __align__(16) float spart[8][FEAT];

    int b = blockIdx.x;
    int tid = threadIdx.x;
    int w = tid >> 5, lane = tid & 31;

    sq[tid] = qt[(size_t)b * FEAT + tid];
    __syncthreads();

    const float4* q4 = (const float4*)sq;
    float4 q0 = q4[lane];
    float4 q1 = q4[lane + 32];

    float4 f[4][2];
    #pragma unroll
    for (int si = 0; si < 4; si++) {
        int s = w * 4 + si;
        int idx = __ldg(neigh + (size_t)b * NSAMP + s);
        const float4* row = (const float4*)(id2feat + (size_t)idx * FEAT);
        f[si][0] = row[lane];
        f[si][1] = row[lane + 32];
        float acc = f[si][0].x * q0.x + f[si][0].y * q0.y +
                    f[si][0].z * q0.z + f[si][0].w * q0.w +
                    f[si][1].x * q1.x + f[si][1].y * q1.y +
                    f[si][1].z * q1.z + f[si][1].w * q1.w;
        #pragma unroll
        for (int o = 16; o; o >>= 1) acc += __shfl_down_sync(FULLMASK, acc, o);
        if (lane == 0) sscore[s] = acc;
    }
    __syncthreads();

    // per-warp redundant softmax over the 32 scores
    float sc = sscore[lane];
    float m = sc;
    #pragma unroll
    for (int o = 16; o; o >>= 1) m = fmaxf(m, __shfl_xor_sync(FULLMASK, m, o));
    float e = __expf(sc - m);
    float sum = e;
    #pragma unroll
    for (int o = 16; o; o >>= 1) sum += __shfl_xor_sync(FULLMASK, sum, o);
    float aval = e / sum;

    float a0 = __shfl_sync(FULLMASK, aval, w * 4 + 0);
    float a1 = __shfl_sync(FULLMASK, aval, w * 4 + 1);
    float a2 = __shfl_sync(FULLMASK, aval, w * 4 + 2);
    float a3 = __shfl_sync(FULLMASK, aval, w * 4 + 3);

    float4 p0, p1;
    p0.x = f[0][0].x * a0 + f[1][0].x * a1 + f[2][0].x * a2 + f[3][0].x * a3;
    p0.y = f[0][0].y * a0 + f[1][0].y * a1 + f[2][0].y * a2 + f[3][0].y * a3;
    p0.z = f[0][0].z * a0 + f[1][0].z * a1 + f[2][0].z * a2 + f[3][0].z * a3;
    p0.w = f[0][0].w * a0 + f[1][0].w * a1 + f[2][0].w * a2 + f[3][0].w * a3;
    p1.x = f[0][1].x * a0 + f[1][1].x * a1 + f[2][1].x * a2 + f[3][1].x * a3;
    p1.y = f[0][1].y * a0 + f[1][1].y * a1 + f[2][1].y * a2 + f[3][1].y * a3;
    p1.z = f[0][1].z * a0 + f[1][1].z * a1 + f[2][1].z * a2 + f[3][1].z * a3;
    p1.w = f[0][1].w * a0 + f[1][1].w * a1 + f[2][1].w * a2 + f[3][1].w * a3;
    ((float4*)spart[w])[lane] = p0;
    ((float4*)spart[w])[lane + 32] = p1;
    __syncthreads();

    float acc = 0.f;
    #pragma unroll
    for (int ww = 0; ww < 8; ww++) acc += spart[ww][tid];
    agg[(size_t)b * FEAT + tid] = acc;
}

// ---------------------------------------------------------------------------
extern "C" void kernel_launch(void* const* d_in, const int* in_sizes, int n_in,
                              void* d_out, int out_size) {
    const int*   nodes   = (const int*)d_in[0];
    const int*   neigh   = (const int*)d_in[1];
    const float* id2feat = (const float*)d_in[2];
    const float* Wq      = (const float*)d_in[3];
    const float* bq      = (const float*)d_in[4];
    const float* Wk      = (const float*)d_in[5];
    const float* Wv      = (const float*)d_in[7];
    const float* bv      = (const float*)d_in[8];
    float* out = (float*)d_out;

    int B = in_sizes[0];  // 10000

    float *gMb, *gMl, *gWvb, *gWvl, *gbqk, *gqt, *gagg;
    cudaGetSymbolAddress((void**)&gMb,  g_Mb);
    cudaGetSymbolAddress((void**)&gMl,  g_Ml);
    cudaGetSymbolAddress((void**)&gWvb, g_Wvb);
    cudaGetSymbolAddress((void**)&gWvl, g_Wvl);
    cudaGetSymbolAddress((void**)&gbqk, g_bqk);
    cudaGetSymbolAddress((void**)&gqt,  g_qt);
    cudaGetSymbolAddress((void**)&gagg, g_agg);

    // 1) M = Wq @ Wk^T (split) ; bqk = bq @ Wk^T ; split Wv
    k_wqwkT<<<dim3(16, 16), dim3(16, 16)>>>(Wq, Wk, gMb, gMl);
    k_bqk<<<FEAT / 8, 256>>>(Wk, bq, gbqk);
    k_splitW<<<FEAT, EMB>>>(Wv, gWvb, gWvl);

    // 2) qt = gather(self) @ M + bqk
    dim3 ggrid(EMB / 64, (B + 127) / 128);
    k_gemm_tc<true><<<ggrid, 256>>>(id2feat, nodes, gMb, gMl, gbqk, gqt, B);

    // 3) scores + softmax + weighted feature aggregation
    k_attn<<<B, 256>>>(id2feat, neigh, gqt, gagg);

    // 4) out = agg @ Wv + bv
    k_gemm_tc<false><<<ggrid, 256>>>(gagg, nullptr, gWvb, gWvl, bv, out, B);
}

// round 8
// speedup vs baseline: 1.1776x; 1.1699x over previous
#include <cuda_runtime.h>
#include <cuda_bf16.h>
#include <cstdint>

#define BATCH_MAX 10000
#define FEAT 256
#define EMB  256
#define NSAMP 32
#define FULLMASK 0xFFFFFFFFu

// Scratch
__device__ float g_Mb[FEAT * EMB];       // big(Wq@Wk^T), n-major k-permuted
__device__ float g_Ml[FEAT * EMB];       // small part
__device__ float g_Wvb[FEAT * EMB];      // big(Wv), n-major k-permuted
__device__ float g_Wvl[FEAT * EMB];
__device__ float g_bqk[FEAT];            // bq @ Wk^T
__device__ float g_qt[BATCH_MAX * FEAT]; // q-tilde
__device__ float g_agg[BATCH_MAX * FEAT];// softmax-weighted feature agg

// k-permutation within each 8-group: frag pair (t, t+4) -> adjacent (2t, 2t+1)
__device__ __forceinline__ int kpos(int k) {
    return (k & ~7) | ((k & 3) << 1) | ((k & 7) >> 2);
}

__device__ __forceinline__ void tf32_split(float x, uint32_t& hi, uint32_t& lo) {
    uint32_t b;
    asm("cvt.rna.tf32.f32 %0, %1;" : "=r"(b) : "f"(x));
    float r = x - __uint_as_float(b);
    uint32_t s;
    asm("cvt.rna.tf32.f32 %0, %1;" : "=r"(s) : "f"(r));
    hi = b; lo = s;
}

__device__ __forceinline__ void mma_tf32(float* d, const uint32_t* a, const uint32_t* b) {
    asm("mma.sync.aligned.m16n8k8.row.col.f32.tf32.tf32.f32 "
        "{%0,%1,%2,%3},{%4,%5,%6,%7},{%8,%9},{%0,%1,%2,%3};"
        : "+f"(d[0]), "+f"(d[1]), "+f"(d[2]), "+f"(d[3])
        : "r"(a[0]), "r"(a[1]), "r"(a[2]), "r"(a[3]), "r"(b[0]), "r"(b[1]));
}

// ---------------------------------------------------------------------------
// M = Wq @ Wk^T (fp32-exact), emitted pre-split into n-major k-permuted layout
// ---------------------------------------------------------------------------
__global__ void k_wqwkT(const float* __restrict__ Wq, const float* __restrict__ Wk,
                        float* __restrict__ Mb, float* __restrict__ Ml) {
    __shared__ float a[16][17];
    __shared__ float b[16][17];
    int tx = threadIdx.x, ty = threadIdx.y;
    int i = blockIdx.y * 16 + ty;   // k-dim of the downstream GEMM
    int j0 = blockIdx.x * 16;
    float acc = 0.f;
    for (int e0 = 0; e0 < FEAT; e0 += 16) {
        a[ty][tx] = Wq[i * FEAT + e0 + tx];
        b[ty][tx] = Wk[(j0 + ty) * FEAT + e0 + tx];
        __syncthreads();
        #pragma unroll
        for (int k = 0; k < 16; k++) acc += a[ty][k] * b[tx][k];
        __syncthreads();
    }
    uint32_t hi, lo;
    tf32_split(acc, hi, lo);
    int p = (j0 + tx) * FEAT + kpos(i);
    Mb[p] = __uint_as_float(hi);
    Ml[p] = __uint_as_float(lo);
}

// ---------------------------------------------------------------------------
// Split Wv [k][n] into n-major k-permuted big/small arrays
// ---------------------------------------------------------------------------
__global__ void k_splitW(const float* __restrict__ W,
                         float* __restrict__ Wb, float* __restrict__ Wl) {
    int k = blockIdx.x, n = threadIdx.x;
    float v = W[k * EMB + n];
    uint32_t hi, lo;
    tf32_split(v, hi, lo);
    int p = n * FEAT + kpos(k);
    Wb[p] = __uint_as_float(hi);
    Wl[p] = __uint_as_float(lo);
}

// ---------------------------------------------------------------------------
// bqk[j] = bq . Wk[j,:]
// ---------------------------------------------------------------------------
__global__ void k_bqk(const float* __restrict__ Wk, const float* __restrict__ bq,
                      float* __restrict__ bqk) {
    int j = blockIdx.x * 8 + (threadIdx.x >> 5);
    int lane = threadIdx.x & 31;
    float s = 0.f;
    #pragma unroll
    for (int e = lane; e < FEAT; e += 32) s += bq[e] * Wk[j * FEAT + e];
    #pragma unroll
    for (int o = 16; o; o >>= 1) s += __shfl_down_sync(FULLMASK, s, o);
    if (lane == 0) bqk[j] = s;
}

// ---------------------------------------------------------------------------
// Tensor-core GEMM (3xTF32, pre-split operands, all-smem inner loop):
//   C[r][j] = sum_k A[row(r)][k]*B[k][j] + bias[j]
//   BM=128, BN=64, BK=16. 256 threads = 8 warps (4m x 2n), warp tile 32x32.
//   APAD=20 -> 80-byte row stride (16B multiple: float4 smem stores legal).
// ---------------------------------------------------------------------------
#define BK 16
#define APAD 20
template <bool GATHER>
__global__ void __launch_bounds__(256, 2) k_gemm_tc(
    const float* __restrict__ A, const int* __restrict__ idx,
    const float* __restrict__ Bb, const float* __restrict__ Bl,
    const float* __restrict__ bias, float* __restrict__ C, int R) {
    __shared__ __align__(16) float As_b[128][APAD];
    __shared__ __align__(16) float As_l[128][APAD];
    __shared__ __align__(16) float Bs_b[64][APAD];
    __shared__ __align__(16) float Bs_l[64][APAD];
    int tid = threadIdx.x;
    int wid = tid >> 5, lane = tid & 31;
    int g = lane >> 2, t = lane & 3;
    int wm = wid & 3, wn = wid >> 2;
    int r0 = blockIdx.y * 128, c0 = blockIdx.x * 64;

    // A loader: 2 threads per row, 8 consecutive floats each (two float4)
    int la_row = tid >> 1;
    int la_q = (tid & 1) * 8;  // k offset within 16-chunk: 0 or 8
    int gr = r0 + la_row;
    bool av = gr < R;
    int grow = av ? (GATHER ? __ldg(idx + gr) : gr) : 0;
    const float* Arow = A + (size_t)grow * FEAT;

    // B loader: 4 threads per n-row, 4 floats each
    int lb_n = tid >> 2;        // 0..63
    int lb_k = (tid & 3) * 4;   // 0,4,8,12 (k-permuted positions, contiguous)
    const float* Bb_src = Bb + (size_t)(c0 + lb_n) * FEAT + lb_k;
    const float* Bl_src = Bl + (size_t)(c0 + lb_n) * FEAT + lb_k;

    float acc[2][4][4];
    #pragma unroll
    for (int mf = 0; mf < 2; mf++)
        #pragma unroll
        for (int nf = 0; nf < 4; nf++)
            #pragma unroll
            for (int q = 0; q < 4; q++) acc[mf][nf][q] = 0.f;

    float4 aR[2];
    #pragma unroll
    for (int q = 0; q < 2; q++)
        aR[q] = av ? *(const float4*)(Arow + la_q + q * 4)
                   : make_float4(0.f, 0.f, 0.f, 0.f);
    float4 bRb = __ldg((const float4*)Bb_src);
    float4 bRl = __ldg((const float4*)Bl_src);

    for (int kt = 0; kt < FEAT / BK; kt++) {
        if (kt) __syncthreads();
        // store A (split + k-permute) and B (straight copy) to smem
        #pragma unroll
        for (int q = 0; q < 2; q++) {
            float vals[4] = {aR[q].x, aR[q].y, aR[q].z, aR[q].w};
            #pragma unroll
            for (int e = 0; e < 4; e++) {
                int j = la_q + q * 4 + e;  // 0..15 local k
                int p = kpos(j);
                uint32_t hi, lo;
                tf32_split(vals[e], hi, lo);
                As_b[la_row][p] = __uint_as_float(hi);
                As_l[la_row][p] = __uint_as_float(lo);
            }
        }
        *(float4*)&Bs_b[lb_n][lb_k] = bRb;
        *(float4*)&Bs_l[lb_n][lb_k] = bRl;
        __syncthreads();
        if (kt < FEAT / BK - 1) {
            #pragma unroll
            for (int q = 0; q < 2; q++)
                aR[q] = av ? *(const float4*)(Arow + (kt + 1) * BK + la_q + q * 4)
                           : make_float4(0.f, 0.f, 0.f, 0.f);
            bRb = __ldg((const float4*)(Bb_src + (kt + 1) * BK));
            bRl = __ldg((const float4*)(Bl_src + (kt + 1) * BK));
        }
        #pragma unroll
        for (int ks = 0; ks < 2; ks++) {
            int kc = ks * 8 + 2 * t;
            uint32_t Ab[2][4], Al[2][4];
            #pragma unroll
            for (int mf = 0; mf < 2; mf++) {
                int rb = wm * 32 + mf * 16;
                float2 h0 = *(const float2*)&As_b[rb + g][kc];
                float2 h1 = *(const float2*)&As_b[rb + 8 + g][kc];
                float2 l0 = *(const float2*)&As_l[rb + g][kc];
                float2 l1 = *(const float2*)&As_l[rb + 8 + g][kc];
                Ab[mf][0] = __float_as_uint(h0.x); Ab[mf][1] = __float_as_uint(h1.x);
                Ab[mf][2] = __float_as_uint(h0.y); Ab[mf][3] = __float_as_uint(h1.y);
                Al[mf][0] = __float_as_uint(l0.x); Al[mf][1] = __float_as_uint(l1.x);
                Al[mf][2] = __float_as_uint(l0.y); Al[mf][3] = __float_as_uint(l1.y);
            }
            #pragma unroll
            for (int nf = 0; nf < 4; nf++) {
                int nb = wn * 32 + nf * 8 + g;
                float2 bb = *(const float2*)&Bs_b[nb][kc];
                float2 bl = *(const float2*)&Bs_l[nb][kc];
                uint32_t Bbf[2] = {__float_as_uint(bb.x), __float_as_uint(bb.y)};
                uint32_t Blf[2] = {__float_as_uint(bl.x), __float_as_uint(bl.y)};
                #pragma unroll
                for (int mf = 0; mf < 2; mf++) {
                    mma_tf32(acc[mf][nf], Ab[mf], Bbf);
                    mma_tf32(acc[mf][nf], Ab[mf], Blf);
                    mma_tf32(acc[mf][nf], Al[mf], Bbf);
                }
            }
        }
    }

    #pragma unroll
    for (int mf = 0; mf < 2; mf++) {
        int r_lo = r0 + wm * 32 + mf * 16 + g;
        int r_hi = r_lo + 8;
        #pragma unroll
        for (int nf = 0; nf < 4; nf++) {
            int c = c0 + wn * 32 + nf * 8 + 2 * t;
            float b0 = bias[c], b1 = bias[c + 1];
            if (r_lo < R) {
                float2 v = make_float2(acc[mf][nf][0] + b0, acc[mf][nf][1] + b1);
                *(float2*)(C + (size_t)r_lo * EMB + c) = v;
            }
            if (r_hi < R) {
                float2 v = make_float2(acc[mf][nf][2] + b0, acc[mf][nf][3] + b1);
                *(float2*)(C + (size_t)r_hi * EMB + c) = v;
            }
        }
    }
}

// ---------------------------------------------------------------------------
// Attention: one block per batch row; features stay in registers.
// ---------------------------------------------------------------------------
__global__ void __launch_bounds__(256) k_attn(
    const float* __restrict__ id2feat, const int* __restrict__ neigh,
    const float* __restrict__ qt, float* __restrict__ agg) {
    __shared__ __align__(16) float sq[FEAT];
    __shared__ float sscore[NSAMP];
    __shared__ __align__(16) float spart[8][FEAT];

    int b = blockIdx.x;
    int tid = threadIdx.x;
    int w = tid >> 5, lane = tid & 31;

    sq[tid] = qt[(size_t)b * FEAT + tid];
    __syncthreads();

    const float4* q4 = (const float4*)sq;
    float4 q0 = q4[lane];
    float4 q1 = q4[lane + 32];

    float4 f[4][2];
    #pragma unroll
    for (int si = 0; si < 4; si++) {
        int s = w * 4 + si;
        int idx = __ldg(neigh + (size_t)b * NSAMP + s);
        const float4* row = (const float4*)(id2feat + (size_t)idx * FEAT);
        f[si][0] = row[lane];
        f[si][1] = row[lane + 32];
        float acc = f[si][0].x * q0.x + f[si][0].y * q0.y +
                    f[si][0].z * q0.z + f[si][0].w * q0.w +
                    f[si][1].x * q1.x + f[si][1].y * q1.y +
                    f[si][1].z * q1.z + f[si][1].w * q1.w;
        #pragma unroll
        for (int o = 16; o; o >>= 1) acc += __shfl_down_sync(FULLMASK, acc, o);
        if (lane == 0) sscore[s] = acc;
    }
    __syncthreads();

    float sc = sscore[lane];
    float m = sc;
    #pragma unroll
    for (int o = 16; o; o >>= 1) m = fmaxf(m, __shfl_xor_sync(FULLMASK, m, o));
    float e = __expf(sc - m);
    float sum = e;
    #pragma unroll
    for (int o = 16; o; o >>= 1) sum += __shfl_xor_sync(FULLMASK, sum, o);
    float aval = e / sum;

    float a0 = __shfl_sync(FULLMASK, aval, w * 4 + 0);
    float a1 = __shfl_sync(FULLMASK, aval, w * 4 + 1);
    float a2 = __shfl_sync(FULLMASK, aval, w * 4 + 2);
    float a3 = __shfl_sync(FULLMASK, aval, w * 4 + 3);

    float4 p0, p1;
    p0.x = f[0][0].x * a0 + f[1][0].x * a1 + f[2][0].x * a2 + f[3][0].x * a3;
    p0.y = f[0][0].y * a0 + f[1][0].y * a1 + f[2][0].y * a2 + f[3][0].y * a3;
    p0.z = f[0][0].z * a0 + f[1][0].z * a1 + f[2][0].z * a2 + f[3][0].z * a3;
    p0.w = f[0][0].w * a0 + f[1][0].w * a1 + f[2][0].w * a2 + f[3][0].w * a3;
    p1.x = f[0][1].x * a0 + f[1][1].x * a1 + f[2][1].x * a2 + f[3][1].x * a3;
    p1.y = f[0][1].y * a0 + f[1][1].y * a1 + f[2][1].y * a2 + f[3][1].y * a3;
    p1.z = f[0][1].z * a0 + f[1][1].z * a1 + f[2][1].z * a2 + f[3][1].z * a3;
    p1.w = f[0][1].w * a0 + f[1][1].w * a1 + f[2][1].w * a2 + f[3][1].w * a3;
    ((float4*)spart[w])[lane] = p0;
    ((float4*)spart[w])[lane + 32] = p1;
    __syncthreads();

    float acc = 0.f;
    #pragma unroll
    for (int ww = 0; ww < 8; ww++) acc += spart[ww][tid];
    agg[(size_t)b * FEAT + tid] = acc;
}

// ---------------------------------------------------------------------------
extern "C" void kernel_launch(void* const* d_in, const int* in_sizes, int n_in,
                              void* d_out, int out_size) {
    const int*   nodes   = (const int*)d_in[0];
    const int*   neigh   = (const int*)d_in[1];
    const float* id2feat = (const float*)d_in[2];
    const float* Wq      = (const float*)d_in[3];
    const float* bq      = (const float*)d_in[4];
    const float* Wk      = (const float*)d_in[5];
    const float* Wv      = (const float*)d_in[7];
    const float* bv      = (const float*)d_in[8];
    float* out = (float*)d_out;

    int B = in_sizes[0];  // 10000

    float *gMb, *gMl, *gWvb, *gWvl, *gbqk, *gqt, *gagg;
    cudaGetSymbolAddress((void**)&gMb,  g_Mb);
    cudaGetSymbolAddress((void**)&gMl,  g_Ml);
    cudaGetSymbolAddress((void**)&gWvb, g_Wvb);
    cudaGetSymbolAddress((void**)&gWvl, g_Wvl);
    cudaGetSymbolAddress((void**)&gbqk, g_bqk);
    cudaGetSymbolAddress((void**)&gqt,  g_qt);
    cudaGetSymbolAddress((void**)&gagg, g_agg);

    // 1) M = Wq @ Wk^T (split) ; bqk = bq @ Wk^T ; split Wv
    k_wqwkT<<<dim3(16, 16), dim3(16, 16)>>>(Wq, Wk, gMb, gMl);
    k_bqk<<<FEAT / 8, 256>>>(Wk, bq, gbqk);
    k_splitW<<<FEAT, EMB>>>(Wv, gWvb, gWvl);

    // 2) qt = gather(self) @ M + bqk
    dim3 ggrid(EMB / 64, (B + 127) / 128);
    k_gemm_tc<true><<<ggrid, 256>>>(id2feat, nodes, gMb, gMl, gbqk, gqt, B);

    // 3) scores + softmax + weighted feature aggregation
    k_attn<<<B, 256>>>(id2feat, neigh, gqt, gagg);

    // 4) out = agg @ Wv + bv
    k_gemm_tc<false><<<ggrid, 256>>>(gagg, nullptr, gWvb, gWvl, bv, out, B);
}

// round 10
// speedup vs baseline: 1.7675x; 1.5009x over previous
#include <cuda_runtime.h>
#include <cuda_fp16.h>
#include <cstdint>

#define BATCH_MAX 10000
#define FEAT 256
#define EMB  256
#define NSAMP 32
#define FULLMASK 0xFFFFFFFFu
#define LO_SCALE 2048.0f
#define LO_INV (1.0f / 2048.0f)

// Scratch: B operands pre-split to fp16 hi/lo (lo scaled by 2048), n-major
__device__ __half g_Mh[EMB * FEAT];
__device__ __half g_Ml[EMB * FEAT];
__device__ __half g_Wvh[EMB * FEAT];
__device__ __half g_Wvl[EMB * FEAT];
__device__ float  g_bqk[FEAT];
__device__ float  g_qt[BATCH_MAX * FEAT];
__device__ float  g_agg[BATCH_MAX * FEAT];

__device__ __forceinline__ void fp16_split(float x, __half& h, __half& l) {
    h = __float2half_rn(x);
    l = __float2half_rn((x - __half2float(h)) * LO_SCALE);
}

__device__ __forceinline__ uint32_t smem_u32(const void* p) {
    return (uint32_t)__cvta_generic_to_shared(p);
}

__device__ __forceinline__ void ldmatrix_x4(uint32_t* r, uint32_t addr) {
    asm volatile("ldmatrix.sync.aligned.m8n8.x4.shared.b16 {%0,%1,%2,%3}, [%4];"
                 : "=r"(r[0]), "=r"(r[1]), "=r"(r[2]), "=r"(r[3]) : "r"(addr));
}

__device__ __forceinline__ void mma_f16(float* d, const uint32_t* a, const uint32_t* b) {
    asm volatile("mma.sync.aligned.m16n8k16.row.col.f32.f16.f16.f32 "
                 "{%0,%1,%2,%3},{%4,%5,%6,%7},{%8,%9},{%0,%1,%2,%3};"
                 : "+f"(d[0]), "+f"(d[1]), "+f"(d[2]), "+f"(d[3])
                 : "r"(a[0]), "r"(a[1]), "r"(a[2]), "r"(a[3]), "r"(b[0]), "r"(b[1]));
}

__device__ __forceinline__ void cp_async16(uint32_t dst, const void* src) {
    asm volatile("cp.async.ca.shared.global [%0], [%1], 16;" :: "r"(dst), "l"(src));
}
__device__ __forceinline__ void cp_commit() { asm volatile("cp.async.commit_group;"); }
__device__ __forceinline__ void cp_wait0() { asm volatile("cp.async.wait_group 0;"); }

// ---------------------------------------------------------------------------
// M = Wq @ Wk^T (fp32-exact), emitted split to fp16 hi/lo, n-major [j][i]
// ---------------------------------------------------------------------------
__global__ void k_wqwkT(const float* __restrict__ Wq, const float* __restrict__ Wk,
                        __half* __restrict__ Mh, __half* __restrict__ Ml) {
    __shared__ float a[16][17];
    __shared__ float b[16][17];
    int tx = threadIdx.x, ty = threadIdx.y;
    int i = blockIdx.y * 16 + ty;   // downstream k
    int j0 = blockIdx.x * 16;       // downstream n
    float acc = 0.f;
    for (int e0 = 0; e0 < FEAT; e0 += 16) {
        a[ty][tx] = Wq[i * FEAT + e0 + tx];
        b[ty][tx] = Wk[(j0 + ty) * FEAT + e0 + tx];
        __syncthreads();
        #pragma unroll
        for (int k = 0; k < 16; k++) acc += a[ty][k] * b[tx][k];
        __syncthreads();
    }
    __half h, l;
    fp16_split(acc, h, l);
    int p = (j0 + tx) * FEAT + i;
    Mh[p] = h;
    Ml[p] = l;
}

// ---------------------------------------------------------------------------
// Split Wv [k][n] into fp16 hi/lo n-major arrays
// ---------------------------------------------------------------------------
__global__ void k_splitW(const float* __restrict__ W,
                         __half* __restrict__ Wh, __half* __restrict__ Wl) {
    int k = blockIdx.x, n = threadIdx.x;
    __half h, l;
    fp16_split(W[k * EMB + n], h, l);
    Wh[n * FEAT + k] = h;
    Wl[n * FEAT + k] = l;
}

// ---------------------------------------------------------------------------
// bqk[j] = bq . Wk[j,:]
// ---------------------------------------------------------------------------
__global__ void k_bqk(const float* __restrict__ Wk, const float* __restrict__ bq,
                      float* __restrict__ bqk) {
    int j = blockIdx.x * 8 + (threadIdx.x >> 5);
    int lane = threadIdx.x & 31;
    float s = 0.f;
    #pragma unroll
    for (int e = lane; e < FEAT; e += 32) s += bq[e] * Wk[j * FEAT + e];
    #pragma unroll
    for (int o = 16; o; o >>= 1) s += __shfl_down_sync(FULLMASK, s, o);
    if (lane == 0) bqk[j] = s;
}

// ---------------------------------------------------------------------------
// fp16 split-GEMM: C[r][j] = sum_k A[row(r)][k]*B[k][j] + bias[j]
//   BM=128, BN=64, BK=16, double-buffered, 8 warps (4m x 2n), warp tile 32x32.
//   A fp32 -> split to fp16 hi / lo*2048 at STS time. B pre-split in global.
//   Fragments via ldmatrix.x4; accM = AhBh, accC = AhBl + AlBh (lo scaled);
//   epilogue: accM + accC/2048 + bias.
// ---------------------------------------------------------------------------
#define BK 16
#define ASTR 24   // halves per smem row (12 words: ldmatrix conflict-free)
template <bool GATHER>
__global__ void __launch_bounds__(256, 2) k_gemm_fp16x2(
    const float* __restrict__ A, const int* __restrict__ idx,
    const __half* __restrict__ Bh_g, const __half* __restrict__ Bl_g,
    const float* __restrict__ bias, float* __restrict__ C, int R) {
    __shared__ __align__(16) __half sAh[2][128][ASTR];
    __shared__ __align__(16) __half sAl[2][128][ASTR];
    __shared__ __align__(16) __half sBh[2][64][ASTR];
    __shared__ __align__(16) __half sBl[2][64][ASTR];

    int tid = threadIdx.x;
    int wid = tid >> 5, lane = tid & 31;
    int wm = wid & 3, wn = wid >> 2;
    int r0 = blockIdx.y * 128, c0 = blockIdx.x * 64;

    // ---- loader roles ----
    // A: thread t -> row t>>1, k-halves (t&1)*8..+7 (8 floats = 2 LDG.128)
    int la_row = tid >> 1;
    int la_k = (tid & 1) * 8;
    int gr = r0 + la_row;
    bool av = gr < R;
    int grow = av ? (GATHER ? __ldg(idx + gr) : gr) : 0;
    const float* Arow = A + (size_t)grow * FEAT + la_k;
    // B: threads 0..127 -> Bh chunks, 128..255 -> Bl chunks.
    //    chunk c: row c>>1, k-offset (c&1)*8 (16 bytes)
    int bc = tid & 127;
    int lb_row = bc >> 1;
    int lb_k = (bc & 1) * 8;
    const __half* Bsrc = ((tid < 128) ? Bh_g : Bl_g) + (size_t)(c0 + lb_row) * FEAT + lb_k;

    float accM[2][4][4], accC[2][4][4];
    #pragma unroll
    for (int mf = 0; mf < 2; mf++)
        #pragma unroll
        for (int nf = 0; nf < 4; nf++)
            #pragma unroll
            for (int q = 0; q < 4; q++) { accM[mf][nf][q] = 0.f; accC[mf][nf][q] = 0.f; }

    // ---- fragment smem addresses (fixed per thread) ----
    int am = lane >> 3, ar = lane & 7;         // matrix idx, row-in-matrix
    int a_roff = ar + (am & 1) * 8;            // + mf*16 + wm*32
    int a_koff = (am >> 1) * 8;
    int b_roff = ar + (am >> 1) * 8;           // + p*16 + wn*32
    int b_koff = (am & 1) * 8;

    // ---- prologue: stage 0 ----
    float4 aR0 = av ? *(const float4*)(Arow) : make_float4(0, 0, 0, 0);
    float4 aR1 = av ? *(const float4*)(Arow + 4) : make_float4(0, 0, 0, 0);
    {
        uint32_t d = smem_u32(&sBh[0][0][0]) + (tid >= 128 ? (uint32_t)(sizeof(sBh) / 2 * 2) : 0u);
        // compute dst directly instead:
    }
    {
        __half* dstB = (tid < 128) ? &sBh[0][lb_row][lb_k] : &sBl[0][lb_row][lb_k];
        cp_async16(smem_u32(dstB), Bsrc);
        cp_commit();
    }
    {
        float v[8] = {aR0.x, aR0.y, aR0.z, aR0.w, aR1.x, aR1.y, aR1.z, aR1.w};
        uint32_t hw[4], lw[4];
        #pragma unroll
        for (int i = 0; i < 4; i++) {
            __half h0, l0, h1, l1;
            fp16_split(v[2 * i], h0, l0);
            fp16_split(v[2 * i + 1], h1, l1);
            hw[i] = (uint32_t)__half_as_ushort(h0) | ((uint32_t)__half_as_ushort(h1) << 16);
            lw[i] = (uint32_t)__half_as_ushort(l0) | ((uint32_t)__half_as_ushort(l1) << 16);
        }
        *(uint4*)&sAh[0][la_row][la_k] = make_uint4(hw[0], hw[1], hw[2], hw[3]);
        *(uint4*)&sAl[0][la_row][la_k] = make_uint4(lw[0], lw[1], lw[2], lw[3]);
    }

    float4 aN0, aN1;
    for (int kt = 0; kt < FEAT / BK; kt++) {
        int buf = kt & 1, nbuf = buf ^ 1;
        cp_wait0();
        __syncthreads();   // stage kt ready; all compute(kt-1) done -> nbuf reusable

        if (kt < FEAT / BK - 1) {
            aN0 = av ? *(const float4*)(Arow + (kt + 1) * BK) : make_float4(0, 0, 0, 0);
            aN1 = av ? *(const float4*)(Arow + (kt + 1) * BK + 4) : make_float4(0, 0, 0, 0);
            __half* dstB = (tid < 128) ? &sBh[nbuf][lb_row][lb_k] : &sBl[nbuf][lb_row][lb_k];
            cp_async16(smem_u32(dstB), Bsrc + (kt + 1) * BK);
            cp_commit();
        }

        // ---- compute stage kt ----
        uint32_t ah[2][4], al[2][4];
        #pragma unroll
        for (int mf = 0; mf < 2; mf++) {
            int row = wm * 32 + mf * 16 + a_roff;
            ldmatrix_x4(ah[mf], smem_u32(&sAh[buf][row][a_koff]));
            ldmatrix_x4(al[mf], smem_u32(&sAl[buf][row][a_koff]));
        }
        #pragma unroll
        for (int p = 0; p < 2; p++) {
            int row = wn * 32 + p * 16 + b_roff;
            uint32_t bh[4], bl[4];
            ldmatrix_x4(bh, smem_u32(&sBh[buf][row][b_koff]));
            ldmatrix_x4(bl, smem_u32(&sBl[buf][row][b_koff]));
            #pragma unroll
            for (int j = 0; j < 2; j++) {
                int nf = 2 * p + j;
                #pragma unroll
                for (int mf = 0; mf < 2; mf++) {
                    mma_f16(accM[mf][nf], ah[mf], &bh[2 * j]);
                    mma_f16(accC[mf][nf], ah[mf], &bl[2 * j]);
                    mma_f16(accC[mf][nf], al[mf], &bh[2 * j]);
                }
            }
        }

        if (kt < FEAT / BK - 1) {
            float v[8] = {aN0.x, aN0.y, aN0.z, aN0.w, aN1.x, aN1.y, aN1.z, aN1.w};
            uint32_t hw[4], lw[4];
            #pragma unroll
            for (int i = 0; i < 4; i++) {
                __half h0, l0, h1, l1;
                fp16_split(v[2 * i], h0, l0);
                fp16_split(v[2 * i + 1], h1, l1);
                hw[i] = (uint32_t)__half_as_ushort(h0) | ((uint32_t)__half_as_ushort(h1) << 16);
                lw[i] = (uint32_t)__half_as_ushort(l0) | ((uint32_t)__half_as_ushort(l1) << 16);
            }
            *(uint4*)&sAh[nbuf][la_row][la_k] = make_uint4(hw[0], hw[1], hw[2], hw[3]);
            *(uint4*)&sAl[nbuf][la_row][la_k] = make_uint4(lw[0], lw[1], lw[2], lw[3]);
        }
    }

    // ---- epilogue ----
    int g = lane >> 2, t = lane & 3;
    #pragma unroll
    for (int mf = 0; mf < 2; mf++) {
        int r_lo = r0 + wm * 32 + mf * 16 + g;
        int r_hi = r_lo + 8;
        #pragma unroll
        for (int nf = 0; nf < 4; nf++) {
            int c = c0 + wn * 32 + nf * 8 + 2 * t;
            float b0 = bias[c], b1 = bias[c + 1];
            if (r_lo < R) {
                float2 v;
                v.x = accM[mf][nf][0] + accC[mf][nf][0] * LO_INV + b0;
                v.y = accM[mf][nf][1] + accC[mf][nf][1] * LO_INV + b1;
                *(float2*)(C + (size_t)r_lo * EMB + c) = v;
            }
            if (r_hi < R) {
                float2 v;
                v.x = accM[mf][nf][2] + accC[mf][nf][2] * LO_INV + b0;
                v.y = accM[mf][nf][3] + accC[mf][nf][3] * LO_INV + b1;
                *(float2*)(C + (size_t)r_hi * EMB + c) = v;
            }
        }
    }
}

// ---------------------------------------------------------------------------
// Attention: one block per batch row; features stay in registers.
// ---------------------------------------------------------------------------
__global__ void __launch_bounds__(256) k_attn(
    const float* __restrict__ id2feat, const int* __restrict__ neigh,
    const float* __restrict__ qt, float* __restrict__ agg) {
    __shared__ __align__(16) float sq[FEAT];
    __shared__ float sscore[NSAMP];
    __shared__ __align__(16) float spart[8][FEAT];

    int b = blockIdx.x;
    int tid = threadIdx.x;
    int w = tid >> 5, lane = tid & 31;

    sq[tid] = qt[(size_t)b * FEAT + tid];
    __syncthreads();

    const float4* q4 = (const float4*)sq;
    float4 q0 = q4[lane];
    float4 q1 = q4[lane + 32];

    float4 f[4][2];
    #pragma unroll
    for (int si = 0; si < 4; si++) {
        int s = w * 4 + si;
        int idx = __ldg(neigh + (size_t)b * NSAMP + s);
        const float4* row = (const float4*)(id2feat + (size_t)idx * FEAT);
        f[si][0] = row[lane];
        f[si][1] = row[lane + 32];
        float acc = f[si][0].x * q0.x + f[si][0].y * q0.y +
                    f[si][0].z * q0.z + f[si][0].w * q0.w +
                    f[si][1].x * q1.x + f[si][1].y * q1.y +
                    f[si][1].z * q1.z + f[si][1].w * q1.w;
        #pragma unroll
        for (int o = 16; o; o >>= 1) acc += __shfl_down_sync(FULLMASK, acc, o);
        if (lane == 0) sscore[s] = acc;
    }
    __syncthreads();

    float sc = sscore[lane];
    float m = sc;
    #pragma unroll
    for (int o = 16; o; o >>= 1) m = fmaxf(m, __shfl_xor_sync(FULLMASK, m, o));
    float e = __expf(sc - m);
    float sum = e;
    #pragma unroll
    for (int o = 16; o; o >>= 1) sum += __shfl_xor_sync(FULLMASK, sum, o);
    float aval = e / sum;

    float a0 = __shfl_sync(FULLMASK, aval, w * 4 + 0);
    float a1 = __shfl_sync(FULLMASK, aval, w * 4 + 1);
    float a2 = __shfl_sync(FULLMASK, aval, w * 4 + 2);
    float a3 = __shfl_sync(FULLMASK, aval, w * 4 + 3);

    float4 p0, p1;
    p0.x = f[0][0].x * a0 + f[1][0].x * a1 + f[2][0].x * a2 + f[3][0].x * a3;
    p0.y = f[0][0].y * a0 + f[1][0].y * a1 + f[2][0].y * a2 + f[3][0].y * a3;
    p0.z = f[0][0].z * a0 + f[1][0].z * a1 + f[2][0].z * a2 + f[3][0].z * a3;
    p0.w = f[0][0].w * a0 + f[1][0].w * a1 + f[2][0].w * a2 + f[3][0].w * a3;
    p1.x = f[0][1].x * a0 + f[1][1].x * a1 + f[2][1].x * a2 + f[3][1].x * a3;
    p1.y = f[0][1].y * a0 + f[1][1].y * a1 + f[2][1].y * a2 + f[3][1].y * a3;
    p1.z = f[0][1].z * a0 + f[1][1].z * a1 + f[2][1].z * a2 + f[3][1].z * a3;
    p1.w = f[0][1].w * a0 + f[1][1].w * a1 + f[2][1].w * a2 + f[3][1].w * a3;
    ((float4*)spart[w])[lane] = p0;
    ((float4*)spart[w])[lane + 32] = p1;
    __syncthreads();

    float acc = 0.f;
    #pragma unroll
    for (int ww = 0; ww < 8; ww++) acc += spart[ww][tid];
    agg[(size_t)b * FEAT + tid] = acc;
}

// ---------------------------------------------------------------------------
extern "C" void kernel_launch(void* const* d_in, const int* in_sizes, int n_in,
                              void* d_out, int out_size) {
    const int*   nodes   = (const int*)d_in[0];
    const int*   neigh   = (const int*)d_in[1];
    const float* id2feat = (const float*)d_in[2];
    const float* Wq      = (const float*)d_in[3];
    const float* bq      = (const float*)d_in[4];
    const float* Wk      = (const float*)d_in[5];
    const float* Wv      = (const float*)d_in[7];
    const float* bv      = (const float*)d_in[8];
    float* out = (float*)d_out;

    int B = in_sizes[0];  // 10000

    __half *gMh, *gMl, *gWvh, *gWvl;
    float *gbqk, *gqt, *gagg;
    cudaGetSymbolAddress((void**)&gMh,  g_Mh);
    cudaGetSymbolAddress((void**)&gMl,  g_Ml);
    cudaGetSymbolAddress((void**)&gWvh, g_Wvh);
    cudaGetSymbolAddress((void**)&gWvl, g_Wvl);
    cudaGetSymbolAddress((void**)&gbqk, g_bqk);
    cudaGetSymbolAddress((void**)&gqt,  g_qt);
    cudaGetSymbolAddress((void**)&gagg, g_agg);

    // 1) M = Wq @ Wk^T (split fp16) ; bqk = bq @ Wk^T ; split Wv
    k_wqwkT<<<dim3(16, 16), dim3(16, 16)>>>(Wq, Wk, gMh, gMl);
    k_bqk<<<FEAT / 8, 256>>>(Wk, bq, gbqk);
    k_splitW<<<FEAT, EMB>>>(Wv, gWvh, gWvl);

    // 2) qt = gather(self) @ M + bqk
    dim3 ggrid(EMB / 64, (B + 127) / 128);
    k_gemm_fp16x2<true><<<ggrid, 256>>>(id2feat, nodes, gMh, gMl, gbqk, gqt, B);

    // 3) scores + softmax + weighted feature aggregation
    k_attn<<<B, 256>>>(id2feat, neigh, gqt, gagg);

    // 4) out = agg @ Wv + bv
    k_gemm_fp16x2<false><<<ggrid, 256>>>(gagg, nullptr, gWvh, gWvl, bv, out, B);
}

// round 11
// speedup vs baseline: 1.7736x; 1.0035x over previous
#include <cuda_runtime.h>
#include <cuda_fp16.h>
#include <cstdint>

#define BATCH_MAX 10000
#define FEAT 256
#define EMB  256
#define NSAMP 32
#define FULLMASK 0xFFFFFFFFu
#define LO_SCALE 2048.0f
#define LO_INV (1.0f / 2048.0f)

// Scratch: B operands pre-split to fp16 hi/lo (lo scaled by 2048), n-major
__device__ __half g_Mh[EMB * FEAT];
__device__ __half g_Ml[EMB * FEAT];
__device__ __half g_Wvh[EMB * FEAT];
__device__ __half g_Wvl[EMB * FEAT];
__device__ float  g_bqk[FEAT];
__device__ float  g_qt[BATCH_MAX * FEAT];
__device__ float  g_agg[BATCH_MAX * FEAT];

__device__ __forceinline__ void fp16_split(float x, __half& h, __half& l) {
    h = __float2half_rn(x);
    l = __float2half_rn((x - __half2float(h)) * LO_SCALE);
}

__device__ __forceinline__ uint32_t smem_u32(const void* p) {
    return (uint32_t)__cvta_generic_to_shared(p);
}

__device__ __forceinline__ void ldmatrix_x4(uint32_t* r, uint32_t addr) {
    asm volatile("ldmatrix.sync.aligned.m8n8.x4.shared.b16 {%0,%1,%2,%3}, [%4];"
                 : "=r"(r[0]), "=r"(r[1]), "=r"(r[2]), "=r"(r[3]) : "r"(addr));
}

__device__ __forceinline__ void mma_f16(float* d, const uint32_t* a, const uint32_t* b) {
    asm volatile("mma.sync.aligned.m16n8k16.row.col.f32.f16.f16.f32 "
                 "{%0,%1,%2,%3},{%4,%5,%6,%7},{%8,%9},{%0,%1,%2,%3};"
                 : "+f"(d[0]), "+f"(d[1]), "+f"(d[2]), "+f"(d[3])
                 : "r"(a[0]), "r"(a[1]), "r"(a[2]), "r"(a[3]), "r"(b[0]), "r"(b[1]));
}

__device__ __forceinline__ void cp_async16(uint32_t dst, const void* src) {
    asm volatile("cp.async.ca.shared.global [%0], [%1], 16;" :: "r"(dst), "l"(src));
}
__device__ __forceinline__ void cp_commit() { asm volatile("cp.async.commit_group;"); }
__device__ __forceinline__ void cp_wait0() { asm volatile("cp.async.wait_group 0;"); }

// ---------------------------------------------------------------------------
// M = Wq @ Wk^T (fp32-exact), emitted split to fp16 hi/lo, n-major [j][i]
// ---------------------------------------------------------------------------
__global__ void k_wqwkT(const float* __restrict__ Wq, const float* __restrict__ Wk,
                        __half* __restrict__ Mh, __half* __restrict__ Ml) {
    __shared__ float a[16][17];
    __shared__ float b[16][17];
    int tx = threadIdx.x, ty = threadIdx.y;
    int i = blockIdx.y * 16 + ty;   // downstream k
    int j0 = blockIdx.x * 16;       // downstream n
    float acc = 0.f;
    for (int e0 = 0; e0 < FEAT; e0 += 16) {
        a[ty][tx] = Wq[i * FEAT + e0 + tx];
        b[ty][tx] = Wk[(j0 + ty) * FEAT + e0 + tx];
        __syncthreads();
        #pragma unroll
        for (int k = 0; k < 16; k++) acc += a[ty][k] * b[tx][k];
        __syncthreads();
    }
    __half h, l;
    fp16_split(acc, h, l);
    int p = (j0 + tx) * FEAT + i;
    Mh[p] = h;
    Ml[p] = l;
}

// ---------------------------------------------------------------------------
// Split Wv [k][n] into fp16 hi/lo n-major arrays
// ---------------------------------------------------------------------------
__global__ void k_splitW(const float* __restrict__ W,
                         __half* __restrict__ Wh, __half* __restrict__ Wl) {
    int k = blockIdx.x, n = threadIdx.x;
    __half h, l;
    fp16_split(W[k * EMB + n], h, l);
    Wh[n * FEAT + k] = h;
    Wl[n * FEAT + k] = l;
}

// ---------------------------------------------------------------------------
// bqk[j] = bq . Wk[j,:]
// ---------------------------------------------------------------------------
__global__ void k_bqk(const float* __restrict__ Wk, const float* __restrict__ bq,
                      float* __restrict__ bqk) {
    int j = blockIdx.x * 8 + (threadIdx.x >> 5);
    int lane = threadIdx.x & 31;
    float s = 0.f;
    #pragma unroll
    for (int e = lane; e < FEAT; e += 32) s += bq[e] * Wk[j * FEAT + e];
    #pragma unroll
    for (int o = 16; o; o >>= 1) s += __shfl_down_sync(FULLMASK, s, o);
    if (lane == 0) bqk[j] = s;
}

// ---------------------------------------------------------------------------
// fp16 split-GEMM: C[r][j] = sum_k A[row(r)][k]*B[k][j] + bias[j]
//   BM=128, BN=64, BK=16, double-buffered, 8 warps (4m x 2n), warp tile 32x32.
//   A fp32 -> split to fp16 hi / lo*2048 at STS time. B pre-split in global.
//   Fragments via ldmatrix.x4; accM = AhBh, accC = AhBl + AlBh (lo scaled);
//   epilogue: accM + accC/2048 + bias.
// ---------------------------------------------------------------------------
#define BK 16
#define ASTR 24   // halves per smem row (12 words: ldmatrix conflict-free)
template <bool GATHER>
__global__ void __launch_bounds__(256, 2) k_gemm_fp16x2(
    const float* __restrict__ A, const int* __restrict__ idx,
    const __half* __restrict__ Bh_g, const __half* __restrict__ Bl_g,
    const float* __restrict__ bias, float* __restrict__ C, int R) {
    __shared__ __align__(16) __half sAh[2][128][ASTR];
    __shared__ __align__(16) __half sAl[2][128][ASTR];
    __shared__ __align__(16) __half sBh[2][64][ASTR];
    __shared__ __align__(16) __half sBl[2][64][ASTR];

    int tid = threadIdx.x;
    int wid = tid >> 5, lane = tid & 31;
    int wm = wid & 3, wn = wid >> 2;
    int r0 = blockIdx.y * 128, c0 = blockIdx.x * 64;

    // ---- loader roles ----
    // A: thread t -> row t>>1, k-halves (t&1)*8..+7 (8 floats = 2 LDG.128)
    int la_row = tid >> 1;
    int la_k = (tid & 1) * 8;
    int gr = r0 + la_row;
    bool av = gr < R;
    int grow = av ? (GATHER ? __ldg(idx + gr) : gr) : 0;
    const float* Arow = A + (size_t)grow * FEAT + la_k;
    // B: threads 0..127 -> Bh chunks, 128..255 -> Bl chunks.
    //    chunk c: row c>>1, k-offset (c&1)*8 (16 bytes)
    int bc = tid & 127;
    int lb_row = bc >> 1;
    int lb_k = (bc & 1) * 8;
    const __half* Bsrc = ((tid < 128) ? Bh_g : Bl_g) + (size_t)(c0 + lb_row) * FEAT + lb_k;

    float accM[2][4][4], accC[2][4][4];
    #pragma unroll
    for (int mf = 0; mf < 2; mf++)
        #pragma unroll
        for (int nf = 0; nf < 4; nf++)
            #pragma unroll
            for (int q = 0; q < 4; q++) { accM[mf][nf][q] = 0.f; accC[mf][nf][q] = 0.f; }

    // ---- fragment smem addresses (fixed per thread) ----
    int am = lane >> 3, ar = lane & 7;         // matrix idx, row-in-matrix
    int a_roff = ar + (am & 1) * 8;            // + mf*16 + wm*32
    int a_koff = (am >> 1) * 8;
    int b_roff = ar + (am >> 1) * 8;           // + p*16 + wn*32
    int b_koff = (am & 1) * 8;

    // ---- prologue: stage 0 ----
    float4 aR0 = av ? *(const float4*)(Arow) : make_float4(0, 0, 0, 0);
    float4 aR1 = av ? *(const float4*)(Arow + 4) : make_float4(0, 0, 0, 0);
    {
        uint32_t d = smem_u32(&sBh[0][0][0]) + (tid >= 128 ? (uint32_t)(sizeof(sBh) / 2 * 2) : 0u);
        // compute dst directly instead:
    }
    {
        __half* dstB = (tid < 128) ? &sBh[0][lb_row][lb_k] : &sBl[0][lb_row][lb_k];
        cp_async16(smem_u32(dstB), Bsrc);
        cp_commit();
    }
    {
        float v[8] = {aR0.x, aR0.y, aR0.z, aR0.w, aR1.x, aR1.y, aR1.z, aR1.w};
        uint32_t hw[4], lw[4];
        #pragma unroll
        for (int i = 0; i < 4; i++) {
            __half h0, l0, h1, l1;
            fp16_split(v[2 * i], h0, l0);
            fp16_split(v[2 * i + 1], h1, l1);
            hw[i] = (uint32_t)__half_as_ushort(h0) | ((uint32_t)__half_as_ushort(h1) << 16);
            lw[i] = (uint32_t)__half_as_ushort(l0) | ((uint32_t)__half_as_ushort(l1) << 16);
        }
        *(uint4*)&sAh[0][la_row][la_k] = make_uint4(hw[0], hw[1], hw[2], hw[3]);
        *(uint4*)&sAl[0][la_row][la_k] = make_uint4(lw[0], lw[1], lw[2], lw[3]);
    }

    float4 aN0, aN1;
    for (int kt = 0; kt < FEAT / BK; kt++) {
        int buf = kt & 1, nbuf = buf ^ 1;
        cp_wait0();
        __syncthreads();   // stage kt ready; all compute(kt-1) done -> nbuf reusable

        if (kt < FEAT / BK - 1) {
            aN0 = av ? *(const float4*)(Arow + (kt + 1) * BK) : make_float4(0, 0, 0, 0);
            aN1 = av ? *(const float4*)(Arow + (kt + 1) * BK + 4) : make_float4(0, 0, 0, 0);
            __half* dstB = (tid < 128) ? &sBh[nbuf][lb_row][lb_k] : &sBl[nbuf][lb_row][lb_k];
            cp_async16(smem_u32(dstB), Bsrc + (kt + 1) * BK);
            cp_commit();
        }

        // ---- compute stage kt ----
        uint32_t ah[2][4], al[2][4];
        #pragma unroll
        for (int mf = 0; mf < 2; mf++) {
            int row = wm * 32 + mf * 16 + a_roff;
            ldmatrix_x4(ah[mf], smem_u32(&sAh[buf][row][a_koff]));
            ldmatrix_x4(al[mf], smem_u32(&sAl[buf][row][a_koff]));
        }
        #pragma unroll
        for (int p = 0; p < 2; p++) {
            int row = wn * 32 + p * 16 + b_roff;
            uint32_t bh[4], bl[4];
            ldmatrix_x4(bh, smem_u32(&sBh[buf][row][b_koff]));
            ldmatrix_x4(bl, smem_u32(&sBl[buf][row][b_koff]));
            #pragma unroll
            for (int j = 0; j < 2; j++) {
                int nf = 2 * p + j;
                #pragma unroll
                for (int mf = 0; mf < 2; mf++) {
                    mma_f16(accM[mf][nf], ah[mf], &bh[2 * j]);
                    mma_f16(accC[mf][nf], ah[mf], &bl[2 * j]);
                    mma_f16(accC[mf][nf], al[mf], &bh[2 * j]);
                }
            }
        }

        if (kt < FEAT / BK - 1) {
            float v[8] = {aN0.x, aN0.y, aN0.z, aN0.w, aN1.x, aN1.y, aN1.z, aN1.w};
            uint32_t hw[4], lw[4];
            #pragma unroll
            for (int i = 0; i < 4; i++) {
                __half h0, l0, h1, l1;
                fp16_split(v[2 * i], h0, l0);
                fp16_split(v[2 * i + 1], h1, l1);
                hw[i] = (uint32_t)__half_as_ushort(h0) | ((uint32_t)__half_as_ushort(h1) << 16);
                lw[i] = (uint32_t)__half_as_ushort(l0) | ((uint32_t)__half_as_ushort(l1) << 16);
            }
            *(uint4*)&sAh[nbuf][la_row][la_k] = make_uint4(hw[0], hw[1], hw[2], hw[3]);
            *(uint4*)&sAl[nbuf][la_row][la_k] = make_uint4(lw[0], lw[1], lw[2], lw[3]);
        }
    }

    // ---- epilogue ----
    int g = lane >> 2, t = lane & 3;
    #pragma unroll
    for (int mf = 0; mf < 2; mf++) {
        int r_lo = r0 + wm * 32 + mf * 16 + g;
        int r_hi = r_lo + 8;
        #pragma unroll
        for (int nf = 0; nf < 4; nf++) {
            int c = c0 + wn * 32 + nf * 8 + 2 * t;
            float b0 = bias[c], b1 = bias[c + 1];
            if (r_lo < R) {
                float2 v;
                v.x = accM[mf][nf][0] + accC[mf][nf][0] * LO_INV + b0;
                v.y = accM[mf][nf][1] + accC[mf][nf][1] * LO_INV + b1;
                *(float2*)(C + (size_t)r_lo * EMB + c) = v;
            }
            if (r_hi < R) {
                float2 v;
                v.x = accM[mf][nf][2] + accC[mf][nf][2] * LO_INV + b0;
                v.y = accM[mf][nf][3] + accC[mf][nf][3] * LO_INV + b1;
                *(float2*)(C + (size_t)r_hi * EMB + c) = v;
            }
        }
    }
}

// ---------------------------------------------------------------------------
// Attention: one block per batch row; features stay in registers.
// ---------------------------------------------------------------------------
__global__ void __launch_bounds__(256) k_attn(
    const float* __restrict__ id2feat, const int* __restrict__ neigh,
    const float* __restrict__ qt, float* __restrict__ agg) {
    __shared__ __align__(16) float sq[FEAT];
    __shared__ float sscore[NSAMP];
    __shared__ __align__(16) float spart[8][FEAT];

    int b = blockIdx.x;
    int tid = threadIdx.x;
    int w = tid >> 5, lane = tid & 31;

    sq[tid] = qt[(size_t)b * FEAT + tid];
    __syncthreads();

    const float4* q4 = (const float4*)sq;
    float4 q0 = q4[lane];
    float4 q1 = q4[lane + 32];

    float4 f[4][2];
    #pragma unroll
    for (int si = 0; si < 4; si++) {
        int s = w * 4 + si;
        int idx = __ldg(neigh + (size_t)b * NSAMP + s);
        const float4* row = (const float4*)(id2feat + (size_t)idx * FEAT);
        f[si][0] = row[lane];
        f[si][1] = row[lane + 32];
        float acc = f[si][0].x * q0.x + f[si][0].y * q0.y +
                    f[si][0].z * q0.z + f[si][0].w * q0.w +
                    f[si][1].x * q1.x + f[si][1].y * q1.y +
                    f[si][1].z * q1.z + f[si][1].w * q1.w;
        #pragma unroll
        for (int o = 16; o; o >>= 1) acc += __shfl_down_sync(FULLMASK, acc, o);
        if (lane == 0) sscore[s] = acc;
    }
    __syncthreads();

    float sc = sscore[lane];
    float m = sc;
    #pragma unroll
    for (int o = 16; o; o >>= 1) m = fmaxf(m, __shfl_xor_sync(FULLMASK, m, o));
    float e = __expf(sc - m);
    float sum = e;
    #pragma unroll
    for (int o = 16; o; o >>= 1) sum += __shfl_xor_sync(FULLMASK, sum, o);
    float aval = e / sum;

    float a0 = __shfl_sync(FULLMASK, aval, w * 4 + 0);
    float a1 = __shfl_sync(FULLMASK, aval, w * 4 + 1);
    float a2 = __shfl_sync(FULLMASK, aval, w * 4 + 2);
    float a3 = __shfl_sync(FULLMASK, aval, w * 4 + 3);

    float4 p0, p1;
    p0.x = f[0][0].x * a0 + f[1][0].x * a1 + f[2][0].x * a2 + f[3][0].x * a3;
    p0.y = f[0][0].y * a0 + f[1][0].y * a1 + f[2][0].y * a2 + f[3][0].y * a3;
    p0.z = f[0][0].z * a0 + f[1][0].z * a1 + f[2][0].z * a2 + f[3][0].z * a3;
    p0.w = f[0][0].w * a0 + f[1][0].w * a1 + f[2][0].w * a2 + f[3][0].w * a3;
    p1.x = f[0][1].x * a0 + f[1][1].x * a1 + f[2][1].x * a2 + f[3][1].x * a3;
    p1.y = f[0][1].y * a0 + f[1][1].y * a1 + f[2][1].y * a2 + f[3][1].y * a3;
    p1.z = f[0][1].z * a0 + f[1][1].z * a1 + f[2][1].z * a2 + f[3][1].z * a3;
    p1.w = f[0][1].w * a0 + f[1][1].w * a1 + f[2][1].w * a2 + f[3][1].w * a3;
    ((float4*)spart[w])[lane] = p0;
    ((float4*)spart[w])[lane + 32] = p1;
    __syncthreads();

    float acc = 0.f;
    #pragma unroll
    for (int ww = 0; ww < 8; ww++) acc += spart[ww][tid];
    agg[(size_t)b * FEAT + tid] = acc;
}

// ---------------------------------------------------------------------------
extern "C" void kernel_launch(void* const* d_in, const int* in_sizes, int n_in,
                              void* d_out, int out_size) {
    const int*   nodes   = (const int*)d_in[0];
    const int*   neigh   = (const int*)d_in[1];
    const float* id2feat = (const float*)d_in[2];
    const float* Wq      = (const float*)d_in[3];
    const float* bq      = (const float*)d_in[4];
    const float* Wk      = (const float*)d_in[5];
    const float* Wv      = (const float*)d_in[7];
    const float* bv      = (const float*)d_in[8];
    float* out = (float*)d_out;

    int B = in_sizes[0];  // 10000

    __half *gMh, *gMl, *gWvh, *gWvl;
    float *gbqk, *gqt, *gagg;
    cudaGetSymbolAddress((void**)&gMh,  g_Mh);
    cudaGetSymbolAddress((void**)&gMl,  g_Ml);
    cudaGetSymbolAddress((void**)&gWvh, g_Wvh);
    cudaGetSymbolAddress((void**)&gWvl, g_Wvl);
    cudaGetSymbolAddress((void**)&gbqk, g_bqk);
    cudaGetSymbolAddress((void**)&gqt,  g_qt);
    cudaGetSymbolAddress((void**)&gagg, g_agg);

    // 1) M = Wq @ Wk^T (split fp16) ; bqk = bq @ Wk^T ; split Wv
    k_wqwkT<<<dim3(16, 16), dim3(16, 16)>>>(Wq, Wk, gMh, gMl);
    k_bqk<<<FEAT / 8, 256>>>(Wk, bq, gbqk);
    k_splitW<<<FEAT, EMB>>>(Wv, gWvh, gWvl);

    // 2) qt = gather(self) @ M + bqk
    dim3 ggrid(EMB / 64, (B + 127) / 128);
    k_gemm_fp16x2<true><<<ggrid, 256>>>(id2feat, nodes, gMh, gMl, gbqk, gqt, B);

    // 3) scores + softmax + weighted feature aggregation
    k_attn<<<B, 256>>>(id2feat, neigh, gqt, gagg);

    // 4) out = agg @ Wv + bv
    k_gemm_fp16x2<false><<<ggrid, 256>>>(gagg, nullptr, gWvh, gWvl, bv, out, B);
}

// round 14
// speedup vs baseline: 1.8967x; 1.0694x over previous
#include <cuda_runtime.h>
#include <cuda_fp16.h>
#include <cstdint>

#define BATCH_MAX 10000
#define FEAT 256
#define EMB  256
#define NSAMP 32
#define FULLMASK 0xFFFFFFFFu
#define LO_SCALE 2048.0f
#define LO_INV (1.0f / 2048.0f)

// Scratch: all GEMM operands pre-split to fp16 hi/lo (lo scaled by 2048)
__device__ __half g_Mh[EMB * FEAT];        // B of GEMM1 (n-major)
__device__ __half g_Ml[EMB * FEAT];
__device__ __half g_Wvh[EMB * FEAT];       // B of GEMM2 (n-major)
__device__ __half g_Wvl[EMB * FEAT];
__device__ __half g_selfh[BATCH_MAX * FEAT]; // A of GEMM1 (gathered self feats)
__device__ __half g_selfl[BATCH_MAX * FEAT];
__device__ __half g_aggh[BATCH_MAX * FEAT];  // A of GEMM2 (attn-weighted feats)
__device__ __half g_aggl[BATCH_MAX * FEAT];
__device__ float  g_bqk[FEAT];
__device__ float  g_qt[BATCH_MAX * FEAT];

__device__ __forceinline__ void fp16_split(float x, __half& h, __half& l) {
    h = __float2half_rn(x);
    l = __float2half_rn((x - __half2float(h)) * LO_SCALE);
}

__device__ __forceinline__ uint32_t smem_u32(const void* p) {
    return (uint32_t)__cvta_generic_to_shared(p);
}

__device__ __forceinline__ void ldmatrix_x4(uint32_t* r, uint32_t addr) {
    asm volatile("ldmatrix.sync.aligned.m8n8.x4.shared.b16 {%0,%1,%2,%3}, [%4];"
                 : "=r"(r[0]), "=r"(r[1]), "=r"(r[2]), "=r"(r[3]) : "r"(addr));
}

__device__ __forceinline__ void mma_f16(float* d, const uint32_t* a, const uint32_t* b) {
    asm volatile("mma.sync.aligned.m16n8k16.row.col.f32.f16.f16.f32 "
                 "{%0,%1,%2,%3},{%4,%5,%6,%7},{%8,%9},{%0,%1,%2,%3};"
                 : "+f"(d[0]), "+f"(d[1]), "+f"(d[2]), "+f"(d[3])
                 : "r"(a[0]), "r"(a[1]), "r"(a[2]), "r"(a[3]), "r"(b[0]), "r"(b[1]));
}

__device__ __forceinline__ void cp_async16(uint32_t dst, const void* src) {
    asm volatile("cp.async.ca.shared.global [%0], [%1], 16;" :: "r"(dst), "l"(src));
}
__device__ __forceinline__ void cp_commit() { asm volatile("cp.async.commit_group;"); }
__device__ __forceinline__ void cp_wait1() { asm volatile("cp.async.wait_group 1;"); }

// ---------------------------------------------------------------------------
// M = Wq @ Wk^T (fp32-exact), emitted split to fp16 hi/lo, n-major [j][i]
// ---------------------------------------------------------------------------
__global__ void k_wqwkT(const float* __restrict__ Wq, const float* __restrict__ Wk,
                        __half* __restrict__ Mh, __half* __restrict__ Ml) {
    __shared__ float a[16][17];
    __shared__ float b[16][17];
    int tx = threadIdx.x, ty = threadIdx.y;
    int i = blockIdx.y * 16 + ty;   // downstream k
    int j0 = blockIdx.x * 16;       // downstream n
    float acc = 0.f;
    for (int e0 = 0; e0 < FEAT; e0 += 16) {
        a[ty][tx] = Wq[i * FEAT + e0 + tx];
        b[ty][tx] = Wk[(j0 + ty) * FEAT + e0 + tx];
        __syncthreads();
        #pragma unroll
        for (int k = 0; k < 16; k++) acc += a[ty][k] * b[tx][k];
        __syncthreads();
    }
    __half h, l;
    fp16_split(acc, h, l);
    int p = (j0 + tx) * FEAT + i;
    Mh[p] = h;
    Ml[p] = l;
}

// ---------------------------------------------------------------------------
// Split Wv [k][n] into fp16 hi/lo n-major arrays
// ---------------------------------------------------------------------------
__global__ void k_splitW(const float* __restrict__ W,
                         __half* __restrict__ Wh, __half* __restrict__ Wl) {
    int k = blockIdx.x, n = threadIdx.x;
    __half h, l;
    fp16_split(W[k * EMB + n], h, l);
    Wh[n * FEAT + k] = h;
    Wl[n * FEAT + k] = l;
}

// ---------------------------------------------------------------------------
// bqk[j] = bq . Wk[j,:]
// ---------------------------------------------------------------------------
__global__ void k_bqk(const float* __restrict__ Wk, const float* __restrict__ bq,
                      float* __restrict__ bqk) {
    int j = blockIdx.x * 8 + (threadIdx.x >> 5);
    int lane = threadIdx.x & 31;
    float s = 0.f;
    #pragma unroll
    for (int e = lane; e < FEAT; e += 32) s += bq[e] * Wk[j * FEAT + e];
    #pragma unroll
    for (int o = 16; o; o >>= 1) s += __shfl_down_sync(FULLMASK, s, o);
    if (lane == 0) bqk[j] = s;
}

// ---------------------------------------------------------------------------
// Gather self feats and split to fp16 hi/lo (one float4 per thread)
// ---------------------------------------------------------------------------
__global__ void k_gatherSplit(const float* __restrict__ feat, const int* __restrict__ nodes,
                              __half* __restrict__ Ah, __half* __restrict__ Al, int B) {
    int gi = blockIdx.x * blockDim.x + threadIdx.x;
    if (gi >= B * (FEAT / 4)) return;
    int row = gi >> 6;
    int c = (gi & 63) * 4;
    float4 v = *(const float4*)(feat + (size_t)__ldg(nodes + row) * FEAT + c);
    __half h0, l0, h1, l1, h2, l2, h3, l3;
    fp16_split(v.x, h0, l0); fp16_split(v.y, h1, l1);
    fp16_split(v.z, h2, l2); fp16_split(v.w, h3, l3);
    uint2 hp, lp;
    hp.x = (uint32_t)__half_as_ushort(h0) | ((uint32_t)__half_as_ushort(h1) << 16);
    hp.y = (uint32_t)__half_as_ushort(h2) | ((uint32_t)__half_as_ushort(h3) << 16);
    lp.x = (uint32_t)__half_as_ushort(l0) | ((uint32_t)__half_as_ushort(l1) << 16);
    lp.y = (uint32_t)__half_as_ushort(l2) | ((uint32_t)__half_as_ushort(l3) << 16);
    *(uint2*)(Ah + (size_t)row * FEAT + c) = hp;
    *(uint2*)(Al + (size_t)row * FEAT + c) = lp;
}

// ---------------------------------------------------------------------------
// fp16 split-GEMM, fully pre-split operands, 3-stage cp.async pipeline,
// dynamic smem (55.3 KB/block): C[r][j] = sum_k A[r][k]*B[k][j] + bias[j]
//   BM=128, BN=64, BK=16. 8 warps (4m x 2n), warp tile 32x32.
//   One group is committed EVERY iteration (empty when nothing to prefetch)
//   so wait_group 1 always drains the group holding stage kt. (R12 bug fix.)
// ---------------------------------------------------------------------------
#define BK 16
#define ASTR 24
#define STAGES 3

struct GemmSmem {
    __half Ah[STAGES][128][ASTR];
    __half Al[STAGES][128][ASTR];
    __half Bh[STAGES][64][ASTR];
    __half Bl[STAGES][64][ASTR];
};
#define GEMM_SMEM_BYTES ((int)sizeof(GemmSmem))

__global__ void __launch_bounds__(256, 2) k_gemm_pre(
    const __half* __restrict__ Ah_g, const __half* __restrict__ Al_g,
    const __half* __restrict__ Bh_g, const __half* __restrict__ Bl_g,
    const float* __restrict__ bias, float* __restrict__ C, int R) {
    extern __shared__ __align__(16) char smem_raw[];
    GemmSmem& S = *reinterpret_cast<GemmSmem*>(smem_raw);

    int tid = threadIdx.x;
    int wid = tid >> 5, lane = tid & 31;
    int wm = wid & 3, wn = wid >> 2;
    int r0 = blockIdx.y * 128, c0 = blockIdx.x * 64;

    // A loader: thread t -> row t>>1, k-offset (t&1)*8 (16 bytes)
    int la_row = tid >> 1;
    int la_k = (tid & 1) * 8;
    int gr = r0 + la_row;
    int grc = gr < R ? gr : R - 1;   // clamp OOB rows to a valid address
    const __half* Ah_src = Ah_g + (size_t)grc * FEAT + la_k;
    const __half* Al_src = Al_g + (size_t)grc * FEAT + la_k;
    // B loader: threads 0..127 -> Bh, 128..255 -> Bl
    int bc = tid & 127;
    int lb_row = bc >> 1;
    int lb_k = (bc & 1) * 8;
    const __half* Bsrc = ((tid < 128) ? Bh_g : Bl_g) + (size_t)(c0 + lb_row) * FEAT + lb_k;

    float accM[2][4][4], accC[2][4][4];
    #pragma unroll
    for (int mf = 0; mf < 2; mf++)
        #pragma unroll
        for (int nf = 0; nf < 4; nf++)
            #pragma unroll
            for (int q = 0; q < 4; q++) { accM[mf][nf][q] = 0.f; accC[mf][nf][q] = 0.f; }

    // fragment smem offsets (fixed per thread)
    int am = lane >> 3, ar = lane & 7;
    int a_roff = ar + (am & 1) * 8;
    int a_koff = (am >> 1) * 8;
    int b_roff = ar + (am >> 1) * 8;
    int b_koff = (am & 1) * 8;

    auto load_stage = [&](int s, int kt) {
        cp_async16(smem_u32(&S.Ah[s][la_row][la_k]), Ah_src + kt * BK);
        cp_async16(smem_u32(&S.Al[s][la_row][la_k]), Al_src + kt * BK);
        if (tid < 128) cp_async16(smem_u32(&S.Bh[s][lb_row][lb_k]), Bsrc + kt * BK);
        else           cp_async16(smem_u32(&S.Bl[s][lb_row][lb_k]), Bsrc + kt * BK);
        cp_commit();
    };

    load_stage(0, 0);
    load_stage(1, 1);

    const int NKT = FEAT / BK;  // 16
    for (int kt = 0; kt < NKT; kt++) {
        int buf = kt % STAGES;
        cp_wait1();          // group for stage kt is complete (see header note)
        __syncthreads();     // all warps finished compute(kt-1); next buf free
        if (kt + 2 < NKT) load_stage((kt + 2) % STAGES, kt + 2);
        else cp_commit();    // empty group keeps wait_group accounting sound

        uint32_t ah[2][4], al[2][4];
        #pragma unroll
        for (int mf = 0; mf < 2; mf++) {
            int row = wm * 32 + mf * 16 + a_roff;
            ldmatrix_x4(ah[mf], smem_u32(&S.Ah[buf][row][a_koff]));
            ldmatrix_x4(al[mf], smem_u32(&S.Al[buf][row][a_koff]));
        }
        #pragma unroll
        for (int p = 0; p < 2; p++) {
            int row = wn * 32 + p * 16 + b_roff;
            uint32_t bh[4], bl[4];
            ldmatrix_x4(bh, smem_u32(&S.Bh[buf][row][b_koff]));
            ldmatrix_x4(bl, smem_u32(&S.Bl[buf][row][b_koff]));
            #pragma unroll
            for (int j = 0; j < 2; j++) {
                int nf = 2 * p + j;
                #pragma unroll
                for (int mf = 0; mf < 2; mf++) {
                    mma_f16(accM[mf][nf], ah[mf], &bh[2 * j]);
                    mma_f16(accC[mf][nf], ah[mf], &bl[2 * j]);
                    mma_f16(accC[mf][nf], al[mf], &bh[2 * j]);
                }
            }
        }
    }

    int g = lane >> 2, t = lane & 3;
    #pragma unroll
    for (int mf = 0; mf < 2; mf++) {
        int r_lo = r0 + wm * 32 + mf * 16 + g;
        int r_hi = r_lo + 8;
        #pragma unroll
        for (int nf = 0; nf < 4; nf++) {
            int c = c0 + wn * 32 + nf * 8 + 2 * t;
            float b0 = bias[c], b1 = bias[c + 1];
            if (r_lo < R) {
                float2 v;
                v.x = accM[mf][nf][0] + accC[mf][nf][0] * LO_INV + b0;
                v.y = accM[mf][nf][1] + accC[mf][nf][1] * LO_INV + b1;
                *(float2*)(C + (size_t)r_lo * EMB + c) = v;
            }
            if (r_hi < R) {
                float2 v;
                v.x = accM[mf][nf][2] + accC[mf][nf][2] * LO_INV + b0;
                v.y = accM[mf][nf][3] + accC[mf][nf][3] * LO_INV + b1;
                *(float2*)(C + (size_t)r_hi * EMB + c) = v;
            }
        }
    }
}

// ---------------------------------------------------------------------------
// Attention: one block per batch row; emits agg pre-split to fp16 hi/lo.
// ---------------------------------------------------------------------------
__global__ void __launch_bounds__(256) k_attn(
    const float* __restrict__ id2feat, const int* __restrict__ neigh,
    const float* __restrict__ qt,
    __half* __restrict__ aggh, __half* __restrict__ aggl) {
    __shared__ __align__(16) float sq[FEAT];
    __shared__ float sscore[NSAMP];
    __shared__ __align__(16) float spart[8][FEAT];

    int b = blockIdx.x;
    int tid = threadIdx.x;
    int w = tid >> 5, lane = tid & 31;

    sq[tid] = qt[(size_t)b * FEAT + tid];
    __syncthreads();

    const float4* q4 = (const float4*)sq;
    float4 q0 = q4[lane];
    float4 q1 = q4[lane + 32];

    float4 f[4][2];
    #pragma unroll
    for (int si = 0; si < 4; si++) {
        int s = w * 4 + si;
        int idx = __ldg(neigh + (size_t)b * NSAMP + s);
        const float4* row = (const float4*)(id2feat + (size_t)idx * FEAT);
        f[si][0] = row[lane];
        f[si][1] = row[lane + 32];
        float acc = f[si][0].x * q0.x + f[si][0].y * q0.y +
                    f[si][0].z * q0.z + f[si][0].w * q0.w +
                    f[si][1].x * q1.x + f[si][1].y * q1.y +
                    f[si][1].z * q1.z + f[si][1].w * q1.w;
        #pragma unroll
        for (int o = 16; o; o >>= 1) acc += __shfl_down_sync(FULLMASK, acc, o);
        if (lane == 0) sscore[s] = acc;
    }
    __syncthreads();

    float sc = sscore[lane];
    float m = sc;
    #pragma unroll
    for (int o = 16; o; o >>= 1) m = fmaxf(m, __shfl_xor_sync(FULLMASK, m, o));
    float e = __expf(sc - m);
    float sum = e;
    #pragma unroll
    for (int o = 16; o; o >>= 1) sum += __shfl_xor_sync(FULLMASK, sum, o);
    float aval = e / sum;

    float a0 = __shfl_sync(FULLMASK, aval, w * 4 + 0);
    float a1 = __shfl_sync(FULLMASK, aval, w * 4 + 1);
    float a2 = __shfl_sync(FULLMASK, aval, w * 4 + 2);
    float a3 = __shfl_sync(FULLMASK, aval, w * 4 + 3);

    float4 p0, p1;
    p0.x = f[0][0].x * a0 + f[1][0].x * a1 + f[2][0].x * a2 + f[3][0].x * a3;
    p0.y = f[0][0].y * a0 + f[1][0].y * a1 + f[2][0].y * a2 + f[3][0].y * a3;
    p0.z = f[0][0].z * a0 + f[1][0].z * a1 + f[2][0].z * a2 + f[3][0].z * a3;
    p0.w = f[0][0].w * a0 + f[1][0].w * a1 + f[2][0].w * a2 + f[3][0].w * a3;
    p1.x = f[0][1].x * a0 + f[1][1].x * a1 + f[2][1].x * a2 + f[3][1].x * a3;
    p1.y = f[0][1].y * a0 + f[1][1].y * a1 + f[2][1].y * a2 + f[3][1].y * a3;
    p1.z = f[0][1].z * a0 + f[1][1].z * a1 + f[2][1].z * a2 + f[3][1].z * a3;
    p1.w = f[0][1].w * a0 + f[1][1].w * a1 + f[2][1].w * a2 + f[3][1].w * a3;
    ((float4*)spart[w])[lane] = p0;
    ((float4*)spart[w])[lane + 32] = p1;
    __syncthreads();

    float acc = 0.f;
    #pragma unroll
    for (int ww = 0; ww < 8; ww++) acc += spart[ww][tid];

    __half h, l;
    fp16_split(acc, h, l);
    aggh[(size_t)b * FEAT + tid] = h;
    aggl[(size_t)b * FEAT + tid] = l;
}

// ---------------------------------------------------------------------------
extern "C" void kernel_launch(void* const* d_in, const int* in_sizes, int n_in,
                              void* d_out, int out_size) {
    const int*   nodes   = (const int*)d_in[0];
    const int*   neigh   = (const int*)d_in[1];
    const float* id2feat = (const float*)d_in[2];
    const float* Wq      = (const float*)d_in[3];
    const float* bq      = (const float*)d_in[4];
    const float* Wk      = (const float*)d_in[5];
    const float* Wv      = (const float*)d_in[7];
    const float* bv      = (const float*)d_in[8];
    float* out = (float*)d_out;

    int B = in_sizes[0];  // 10000

    __half *gMh, *gMl, *gWvh, *gWvl, *gSh, *gSl, *gAh, *gAl;
    float *gbqk, *gqt;
    cudaGetSymbolAddress((void**)&gMh,  g_Mh);
    cudaGetSymbolAddress((void**)&gMl,  g_Ml);
    cudaGetSymbolAddress((void**)&gWvh, g_Wvh);
    cudaGetSymbolAddress((void**)&gWvl, g_Wvl);
    cudaGetSymbolAddress((void**)&gSh,  g_selfh);
    cudaGetSymbolAddress((void**)&gSl,  g_selfl);
    cudaGetSymbolAddress((void**)&gAh,  g_aggh);
    cudaGetSymbolAddress((void**)&gAl,  g_aggl);
    cudaGetSymbolAddress((void**)&gbqk, g_bqk);
    cudaGetSymbolAddress((void**)&gqt,  g_qt);

    // allow >48KB dynamic smem for the GEMM (attribute set, not an allocation)
    cudaFuncSetAttribute(k_gemm_pre, cudaFuncAttributeMaxDynamicSharedMemorySize,
                         GEMM_SMEM_BYTES);

    // 1) preprocessing: M = Wq@Wk^T (split), bqk, split Wv, gather+split self
    k_wqwkT<<<dim3(16, 16), dim3(16, 16)>>>(Wq, Wk, gMh, gMl);
    k_bqk<<<FEAT / 8, 256>>>(Wk, bq, gbqk);
    k_splitW<<<FEAT, EMB>>>(Wv, gWvh, gWvl);
    k_gatherSplit<<<(B * 64 + 255) / 256, 256>>>(id2feat, nodes, gSh, gSl, B);

    // 2) qt = self @ M + bqk
    dim3 ggrid(EMB / 64, (B + 127) / 128);
    k_gemm_pre<<<ggrid, 256, GEMM_SMEM_BYTES>>>(gSh, gSl, gMh, gMl, gbqk, gqt, B);

    // 3) scores + softmax + weighted feature aggregation (emits split agg)
    k_attn<<<B, 256>>>(id2feat, neigh, gqt, gAh, gAl);

    // 4) out = agg @ Wv + bv
    k_gemm_pre<<<ggrid, 256, GEMM_SMEM_BYTES>>>(gAh, gAl, gWvh, gWvl, bv, out, B);
}